// round 5
// baseline (speedup 1.0000x reference)
#include <cuda_runtime.h>
#include <stdint.h>
#include <math.h>

// ---------------- problem constants ----------------
#define T_   128
#define B_   512
#define DIN_ 512
#define H_   512
#define DM_  256
#define HYP_ 256
#define L_   100

// output offsets (floats)
#define OUT_N      ((int64_t)T_*B_*H_)
#define OFF_HT     (OUT_N)
#define OFF_CT     (OFF_HT + (int64_t)B_*H_)
#define OFF_HHAT   (OFF_CT + (int64_t)B_*H_)

// ---------------- scratch (device globals) ----------------
__device__ float g_q   [(size_t)T_*B_*HYP_];
__device__ float g_k   [(size_t)B_*L_*HYP_];
__device__ float g_att [(size_t)T_*B_*DM_];
__device__ float g_mpre[(size_t)T_*B_*HYP_];
__device__ float g_wx  [(size_t)T_*B_*4*H_];
__device__ float g_WzT [3*4*HYP_*HYP_];
__device__ float g_Wcomp[3*4*H_*HYP_];
__device__ float g_bcomp[3*4*H_];
__device__ float g_merged[B_*HYP_];
__device__ float g_D  [(size_t)B_*3*4*H_];
__device__ float g_wh [(size_t)B_*4*H_];
__device__ float g_h  [B_*H_];
__device__ float g_c  [B_*H_];

// ---------------- packed f32x2 helpers (sm_100+) ----------------
typedef unsigned long long u64;

__device__ __forceinline__ u64 dup2f(float a) {
    u64 r; asm("mov.b64 %0, {%1, %1};" : "=l"(r) : "f"(a)); return r;
}
__device__ __forceinline__ void fma2(u64 &c, u64 a, u64 b) {
    asm("fma.rn.f32x2 %0, %1, %2, %0;" : "+l"(c) : "l"(a), "l"(b));
}
__device__ __forceinline__ void unpk(u64 v, float &lo, float &hi) {
    asm("mov.b64 {%0, %1}, %2;" : "=f"(lo), "=f"(hi) : "l"(v));
}

// ---------------- 128x128x16 double-buffered FFMA2 GEMM core ----------------
// A operand is staged into shared memory PRE-DUPLICATED as u64 (both halves
// equal), so the inner loop issues no broadcast MOVs: just LDS + FFMA2.
// C[m,n] = sum_k A[m,k] * W[n,k]  (+bias[n]) (+addsrc[m,n]) (relu)
__device__ __forceinline__ void gemm128_core(
    const float* __restrict__ A, int lda,
    const float* __restrict__ W, int ldw,
    float* __restrict__ C, int ldc,
    const float* __restrict__ bias,
    const float* __restrict__ addsrc, int ldadd,
    int K, int relu, int64_t m0, int n0,
    u64 (*As)[16][128], float (*Ws)[16][128])
{
    const int tid = threadIdx.x;
    const int lr = tid >> 1;               // 0..127
    const int lk = (tid & 1) << 3;         // 0 or 8
    const float* Ap = A + (m0 + lr) * (int64_t)lda + lk;
    const float* Wp = W + (int64_t)(n0 + lr) * ldw + lk;
    const int tx = tid & 15, ty = tid >> 4;

    u64 acc[8][4];
    #pragma unroll
    for (int i = 0; i < 8; i++)
        #pragma unroll
        for (int j = 0; j < 4; j++) acc[i][j] = 0ull;

    float4 pa0 = *(const float4*)(Ap);
    float4 pa1 = *(const float4*)(Ap + 4);
    float4 pw0 = *(const float4*)(Wp);
    float4 pw1 = *(const float4*)(Wp + 4);

    {
        float am[8] = {pa0.x, pa0.y, pa0.z, pa0.w, pa1.x, pa1.y, pa1.z, pa1.w};
        #pragma unroll
        for (int i = 0; i < 8; i++) As[0][lk + i][lr] = dup2f(am[i]);
        Ws[0][lk+0][lr]=pw0.x; Ws[0][lk+1][lr]=pw0.y; Ws[0][lk+2][lr]=pw0.z; Ws[0][lk+3][lr]=pw0.w;
        Ws[0][lk+4][lr]=pw1.x; Ws[0][lk+5][lr]=pw1.y; Ws[0][lk+6][lr]=pw1.z; Ws[0][lk+7][lr]=pw1.w;
    }
    __syncthreads();

    int buf = 0;
    for (int k0 = 0; k0 < K; k0 += 16) {
        const bool more = (k0 + 16) < K;
        if (more) {
            pa0 = *(const float4*)(Ap + k0 + 16);
            pa1 = *(const float4*)(Ap + k0 + 20);
            pw0 = *(const float4*)(Wp + k0 + 16);
            pw1 = *(const float4*)(Wp + k0 + 20);
        }
        #pragma unroll
        for (int kk = 0; kk < 16; kk++) {
            const u64* ap = &As[buf][kk][ty << 3];
            const u64* bp = (const u64*)&Ws[buf][kk][tx << 3];
            u64 b0 = bp[0], b1 = bp[1], b2 = bp[2], b3 = bp[3];
            u64 am[8];
            #pragma unroll
            for (int i = 0; i < 8; i++) am[i] = ap[i];
            #pragma unroll
            for (int i = 0; i < 8; i++) {
                fma2(acc[i][0], am[i], b0);
                fma2(acc[i][1], am[i], b1);
                fma2(acc[i][2], am[i], b2);
                fma2(acc[i][3], am[i], b3);
            }
        }
        if (more) {
            const int nb = buf ^ 1;
            float am[8] = {pa0.x, pa0.y, pa0.z, pa0.w, pa1.x, pa1.y, pa1.z, pa1.w};
            #pragma unroll
            for (int i = 0; i < 8; i++) As[nb][lk + i][lr] = dup2f(am[i]);
            Ws[nb][lk+0][lr]=pw0.x; Ws[nb][lk+1][lr]=pw0.y; Ws[nb][lk+2][lr]=pw0.z; Ws[nb][lk+3][lr]=pw0.w;
            Ws[nb][lk+4][lr]=pw1.x; Ws[nb][lk+5][lr]=pw1.y; Ws[nb][lk+6][lr]=pw1.z; Ws[nb][lk+7][lr]=pw1.w;
            __syncthreads();
            buf = nb;
        }
    }

    const int nc = n0 + (tx << 3);
    float bv[8];
    if (bias) {
        float4 q0 = *(const float4*)&bias[nc];
        float4 q1 = *(const float4*)&bias[nc + 4];
        bv[0]=q0.x; bv[1]=q0.y; bv[2]=q0.z; bv[3]=q0.w;
        bv[4]=q1.x; bv[5]=q1.y; bv[6]=q1.z; bv[7]=q1.w;
    } else {
        #pragma unroll
        for (int j = 0; j < 8; j++) bv[j] = 0.f;
    }
    #pragma unroll
    for (int i = 0; i < 8; i++) {
        const int64_t row = m0 + (ty << 3) + i;
        float r[8];
        #pragma unroll
        for (int p = 0; p < 4; p++) {
            float lo, hi; unpk(acc[i][p], lo, hi);
            r[2*p]   = lo + bv[2*p];
            r[2*p+1] = hi + bv[2*p+1];
        }
        if (addsrc) {
            const float* s = addsrc + row * (int64_t)ldadd + nc;
            float4 s0 = *(const float4*)s, s1 = *(const float4*)(s + 4);
            r[0]+=s0.x; r[1]+=s0.y; r[2]+=s0.z; r[3]+=s0.w;
            r[4]+=s1.x; r[5]+=s1.y; r[6]+=s1.z; r[7]+=s1.w;
        }
        if (relu) {
            #pragma unroll
            for (int j = 0; j < 8; j++) r[j] = fmaxf(r[j], 0.f);
        }
        float4 o0 = make_float4(r[0], r[1], r[2], r[3]);
        float4 o1 = make_float4(r[4], r[5], r[6], r[7]);
        *(float4*)&C[row * (int64_t)ldc + nc]     = o0;
        *(float4*)&C[row * (int64_t)ldc + nc + 4] = o1;
    }
}

__global__ void __launch_bounds__(256, 2)
sgemm128(const float* __restrict__ A, int lda, int64_t sA,
         const float* __restrict__ W, int ldw, int64_t sW,
         float* __restrict__ C, int ldc, int64_t sC,
         const float* __restrict__ bias,
         const float* __restrict__ addsrc, int ldadd,
         int K, int relu)
{
    __shared__ u64   As[2][16][128];   // 32 KB
    __shared__ float Ws[2][16][128];   // 16 KB
    const int bz = blockIdx.z;
    gemm128_core(A + bz * sA, lda, W + bz * sW, ldw, C + bz * sC, ldc,
                 bias, addsrc, ldadd, K, relu,
                 (int64_t)blockIdx.y * 128, blockIdx.x * 128, As, Ws);
}

// combined per-step kernel: wh = h @ w_h^T  |  D = merged @ Wcomp^T + bcomp
__global__ void __launch_bounds__(256, 2)
sgemm_dwh(const float* __restrict__ h, const float* __restrict__ w_h,
          const float* __restrict__ merged, const float* __restrict__ Wcomp,
          const float* __restrict__ bcomp,
          float* __restrict__ wh, float* __restrict__ D)
{
    __shared__ u64   As[2][16][128];
    __shared__ float Ws[2][16][128];
    const int bx = blockIdx.x;
    const int64_t m0 = (int64_t)blockIdx.y * 128;
    if (bx < 16) {
        gemm128_core(h, H_, w_h, H_, wh, 4*H_, nullptr, nullptr, 0,
                     H_, 0, m0, bx * 128, As, Ws);
    } else {
        gemm128_core(merged, HYP_, Wcomp, HYP_, D, 3*4*H_, bcomp, nullptr, 0,
                     HYP_, 0, m0, (bx - 16) * 128, As, Ws);
    }
}

// ---------------- small GEMM: merged = relu(mpre + h @ Wm3^T) ----------------
// 32x64 tile, 128 threads, micro 4x4 with f32x2, double-buffered, A dup'd.
__global__ void __launch_bounds__(128)
sgemm_merged(const float* __restrict__ h, const float* __restrict__ Wm3,
             const float* __restrict__ mpre, float* __restrict__ mg)
{
    __shared__ u64   As[2][16][32];    // 8 KB
    __shared__ float Ws[2][16][64];    // 8 KB
    const int n0 = blockIdx.x << 6;
    const int m0 = blockIdx.y << 5;
    const int tid = threadIdx.x;
    const int ar = tid >> 2, ak = (tid & 3) << 2;
    const int wr = tid >> 1, wk = (tid & 1) << 3;
    const float* Ap = h + (m0 + ar) * H_ + ak;
    const float* Wp = Wm3 + (int64_t)(n0 + wr) * (DIN_ + DM_ + H_) + wk;
    const int tx = tid & 15, ty = tid >> 4;

    u64 acc[4][2];
    #pragma unroll
    for (int i = 0; i < 4; i++) { acc[i][0] = 0ull; acc[i][1] = 0ull; }

    float4 a  = *(const float4*)(Ap);
    float4 w0 = *(const float4*)(Wp);
    float4 w1 = *(const float4*)(Wp + 4);
    As[0][ak+0][ar]=dup2f(a.x); As[0][ak+1][ar]=dup2f(a.y);
    As[0][ak+2][ar]=dup2f(a.z); As[0][ak+3][ar]=dup2f(a.w);
    Ws[0][wk+0][wr]=w0.x; Ws[0][wk+1][wr]=w0.y; Ws[0][wk+2][wr]=w0.z; Ws[0][wk+3][wr]=w0.w;
    Ws[0][wk+4][wr]=w1.x; Ws[0][wk+5][wr]=w1.y; Ws[0][wk+6][wr]=w1.z; Ws[0][wk+7][wr]=w1.w;
    __syncthreads();

    int buf = 0;
    for (int k0 = 0; k0 < H_; k0 += 16) {
        const bool more = (k0 + 16) < H_;
        if (more) {
            a  = *(const float4*)(Ap + k0 + 16);
            w0 = *(const float4*)(Wp + k0 + 16);
            w1 = *(const float4*)(Wp + k0 + 20);
        }
        #pragma unroll
        for (int kk = 0; kk < 16; kk++) {
            const u64* ap = &As[buf][kk][ty << 2];
            const u64* bp = (const u64*)&Ws[buf][kk][tx << 2];
            u64 b0 = bp[0], b1 = bp[1];
            #pragma unroll
            for (int i = 0; i < 4; i++) {
                u64 av = ap[i];
                fma2(acc[i][0], av, b0);
                fma2(acc[i][1], av, b1);
            }
        }
        if (more) {
            const int nb = buf ^ 1;
            As[nb][ak+0][ar]=dup2f(a.x); As[nb][ak+1][ar]=dup2f(a.y);
            As[nb][ak+2][ar]=dup2f(a.z); As[nb][ak+3][ar]=dup2f(a.w);
            Ws[nb][wk+0][wr]=w0.x; Ws[nb][wk+1][wr]=w0.y; Ws[nb][wk+2][wr]=w0.z; Ws[nb][wk+3][wr]=w0.w;
            Ws[nb][wk+4][wr]=w1.x; Ws[nb][wk+5][wr]=w1.y; Ws[nb][wk+6][wr]=w1.z; Ws[nb][wk+7][wr]=w1.w;
            __syncthreads();
            buf = nb;
        }
    }
    const int nc = n0 + (tx << 2);
    #pragma unroll
    for (int i = 0; i < 4; i++) {
        const int row = m0 + (ty << 2) + i;
        float4 s = *(const float4*)&mpre[row * HYP_ + nc];
        float lo0, hi0, lo1, hi1;
        unpk(acc[i][0], lo0, hi0);
        unpk(acc[i][1], lo1, hi1);
        float4 r;
        r.x = fmaxf(lo0 + s.x, 0.f);
        r.y = fmaxf(hi0 + s.y, 0.f);
        r.z = fmaxf(lo1 + s.z, 0.f);
        r.w = fmaxf(hi1 + s.w, 0.f);
        *(float4*)&mg[row * HYP_ + nc] = r;
    }
}

// ---------------- fused attention ----------------
__global__ void __launch_bounds__(256)
attn_kernel(const float* __restrict__ q, const float* __restrict__ k,
            const float* __restrict__ meta, const int* __restrict__ inp,
            float* __restrict__ att)
{
    const int tb = blockIdx.x;
    const int b  = tb & (B_ - 1);
    const int tid = threadIdx.x;
    __shared__ float qs[HYP_];
    __shared__ float sc[128];

    qs[tid] = q[(int64_t)tb * HYP_ + tid] * 0.0625f;
    __syncthreads();

    const int lane = tid & 31, wrp = tid >> 5;
    for (int l = wrp; l < L_; l += 8) {
        const float* kp = k + ((int64_t)b * L_ + l) * HYP_;
        float s = 0.f;
        #pragma unroll
        for (int e = 0; e < HYP_ / 32; e++)
            s += qs[lane + 32 * e] * kp[lane + 32 * e];
        #pragma unroll
        for (int o = 16; o; o >>= 1) s += __shfl_xor_sync(0xffffffffu, s, o);
        if (lane == 0) sc[l] = (inp[b * L_ + l] == 0) ? -1e9f : s;
    }
    __syncthreads();

    if (tid < 32) {
        float v[4]; float m = -3.0e38f;
        #pragma unroll
        for (int j = 0; j < 4; j++) {
            int l = tid + 32 * j;
            v[j] = (l < L_) ? sc[l] : -3.0e38f;
            m = fmaxf(m, v[j]);
        }
        #pragma unroll
        for (int o = 16; o; o >>= 1) m = fmaxf(m, __shfl_xor_sync(0xffffffffu, m, o));
        float s = 0.f;
        #pragma unroll
        for (int j = 0; j < 4; j++) { v[j] = expf(v[j] - m); s += v[j]; }
        #pragma unroll
        for (int o = 16; o; o >>= 1) s += __shfl_xor_sync(0xffffffffu, s, o);
        const float inv = 1.0f / s;
        #pragma unroll
        for (int j = 0; j < 4; j++) {
            int l = tid + 32 * j;
            if (l < L_) sc[l] = v[j] * inv;
        }
    }
    __syncthreads();

    float acc = 0.f;
    const float* mp = meta + (int64_t)b * L_ * DM_ + tid;
    #pragma unroll 4
    for (int l = 0; l < L_; l++) acc += sc[l] * mp[(int64_t)l * DM_];
    att[(int64_t)tb * DM_ + tid] = acc;
}

// ---------------- weight preprocessing ----------------
__global__ void transpose_wz(const float* __restrict__ Wzh, const float* __restrict__ Wzx,
                             const float* __restrict__ Wzb, float* __restrict__ WzT)
{
    int idx = blockIdx.x * 256 + threadIdx.x;
    int s  = idx / (4 * HYP_ * HYP_);
    int r  = idx % (4 * HYP_ * HYP_);
    int kk = r / (HYP_ * HYP_);
    int r2 = r % (HYP_ * HYP_);
    int z  = r2 / HYP_;
    int z2 = r2 % HYP_;
    const float* Wz = (s == 0) ? Wzh : ((s == 1) ? Wzx : Wzb);
    WzT[idx] = Wz[(kk * HYP_ + z2) * HYP_ + z];
}

__global__ void comp_bias(const float* __restrict__ bzh, const float* __restrict__ Wdh,
                          const float* __restrict__ bzx, const float* __restrict__ Wdx,
                          const float* __restrict__ bdb, float* __restrict__ bcomp)
{
    int n = blockIdx.x * 256 + threadIdx.x;
    if (n < 2048) {
        int kk = n >> 9;
        float s = 0.f;
        for (int z = 0; z < HYP_; z++) s += bzh[kk * HYP_ + z] * Wdh[n * HYP_ + z];
        bcomp[n] = s;
    } else if (n < 4096) {
        int m = n - 2048; int kk = m >> 9;
        float s = 0.f;
        for (int z = 0; z < HYP_; z++) s += bzx[kk * HYP_ + z] * Wdx[m * HYP_ + z];
        bcomp[n] = s;
    } else {
        bcomp[n] = bdb[n - 4096];
    }
}

__global__ void init_zero(float* __restrict__ h, float* __restrict__ c,
                          float* __restrict__ tail)
{
    int i = blockIdx.x * 256 + threadIdx.x;
    h[i] = 0.f; c[i] = 0.f; tail[i] = 0.f;
}

// ---------------- fused elementwise + LayerNorm + LSTM cell ----------------
__global__ void __launch_bounds__(512)
lstm_step(const float* __restrict__ D, const float* __restrict__ wh,
          const float* __restrict__ wx, const float* __restrict__ lng,
          const float* __restrict__ lnb, float* __restrict__ h,
          float* __restrict__ c, float* __restrict__ out,
          float* __restrict__ hT, float* __restrict__ cT)
{
    const int b  = blockIdx.x;
    const int hh = threadIdx.x;
    const int lane = hh & 31, wrp = hh >> 5;
    __shared__ float red[4][16];
    __shared__ float mu_s[4], iv_s[4];

    float y[4];
    #pragma unroll
    for (int k = 0; k < 4; k++) {
        const int idx = k * H_ + hh;
        const int64_t base = (int64_t)b * 6144;
        float dh = D[base + idx];
        float dx = D[base + 2048 + idx];
        float db = D[base + 4096 + idx];
        y[k] = dh * wh[(int64_t)b * 2048 + idx] + dx * wx[(int64_t)b * 2048 + idx] + db;
    }
    #pragma unroll
    for (int k = 0; k < 4; k++) {
        float s = y[k];
        #pragma unroll
        for (int o = 16; o; o >>= 1) s += __shfl_xor_sync(0xffffffffu, s, o);
        if (lane == 0) red[k][wrp] = s;
    }
    __syncthreads();
    if (hh < 4) {
        float s = 0.f;
        #pragma unroll
        for (int w = 0; w < 16; w++) s += red[hh][w];
        mu_s[hh] = s * (1.0f / H_);
    }
    __syncthreads();
    const float mu[4] = {mu_s[0], mu_s[1], mu_s[2], mu_s[3]};
    #pragma unroll
    for (int k = 0; k < 4; k++) {
        float d = y[k] - mu[k];
        float s = d * d;
        #pragma unroll
        for (int o = 16; o; o >>= 1) s += __shfl_xor_sync(0xffffffffu, s, o);
        if (lane == 0) red[k][wrp] = s;
    }
    __syncthreads();
    if (hh < 4) {
        float s = 0.f;
        #pragma unroll
        for (int w = 0; w < 16; w++) s += red[hh][w];
        iv_s[hh] = rsqrtf(s * (1.0f / H_) + 1e-5f);
    }
    __syncthreads();

    float yn[4];
    #pragma unroll
    for (int k = 0; k < 4; k++)
        yn[k] = (y[k] - mu[k]) * iv_s[k] * lng[k * H_ + hh] + lnb[k * H_ + hh];

    const float ig = 1.f / (1.f + expf(-yn[0]));
    const float fg = 1.f / (1.f + expf(-yn[1]));
    const float gg = tanhf(yn[2]);
    const float og = 1.f / (1.f + expf(-yn[3]));

    const int64_t bi = (int64_t)b * H_ + hh;
    const float cn = fg * c[bi] + ig * gg;
    const float hn = og * tanhf(cn);
    c[bi] = cn;  h[bi] = hn;  out[bi] = hn;
    if (hT) { hT[bi] = hn; cT[bi] = cn; }
}

// ---------------- host driver ----------------
extern "C" void kernel_launch(void* const* d_in, const int* in_sizes, int n_in,
                              void* d_out, int out_size)
{
    const float* x    = (const float*)d_in[0];
    const float* meta = (const float*)d_in[1];
    const int*   inp  = (const int*)  d_in[2];
    const float* Wq   = (const float*)d_in[3];
    const float* bq   = (const float*)d_in[4];
    const float* Wk   = (const float*)d_in[5];
    const float* bk   = (const float*)d_in[6];
    const float* Wm   = (const float*)d_in[7];
    const float* bm   = (const float*)d_in[8];
    const float* Wzh  = (const float*)d_in[9];
    const float* bzh  = (const float*)d_in[10];
    const float* Wzx  = (const float*)d_in[11];
    const float* bzx  = (const float*)d_in[12];
    const float* Wzb  = (const float*)d_in[13];
    const float* Wdh  = (const float*)d_in[14];
    const float* Wdx  = (const float*)d_in[15];
    const float* Wdb  = (const float*)d_in[16];
    const float* bdb  = (const float*)d_in[17];
    const float* w_h  = (const float*)d_in[18];
    const float* w_x  = (const float*)d_in[19];
    const float* lng  = (const float*)d_in[20];
    const float* lnb  = (const float*)d_in[21];
    float* out = (float*)d_out;

    float *pq, *pk, *patt, *pmpre, *pwx, *pWzT, *pWcomp, *pbcomp,
          *pmerged, *pD, *pwh, *ph, *pc;
    cudaGetSymbolAddress((void**)&pq,     g_q);
    cudaGetSymbolAddress((void**)&pk,     g_k);
    cudaGetSymbolAddress((void**)&patt,   g_att);
    cudaGetSymbolAddress((void**)&pmpre,  g_mpre);
    cudaGetSymbolAddress((void**)&pwx,    g_wx);
    cudaGetSymbolAddress((void**)&pWzT,   g_WzT);
    cudaGetSymbolAddress((void**)&pWcomp, g_Wcomp);
    cudaGetSymbolAddress((void**)&pbcomp, g_bcomp);
    cudaGetSymbolAddress((void**)&pmerged,g_merged);
    cudaGetSymbolAddress((void**)&pD,     g_D);
    cudaGetSymbolAddress((void**)&pwh,    g_wh);
    cudaGetSymbolAddress((void**)&ph,     g_h);
    cudaGetSymbolAddress((void**)&pc,     g_c);

    init_zero<<<1024, 256>>>(ph, pc, out + OFF_HHAT);

    // ---- weight preprocessing ----
    transpose_wz<<<3072, 256>>>(Wzh, Wzx, Wzb, pWzT);
    {
        dim3 gW(HYP_ / 128, H_ / 128, 4);
        const float* Wd[3] = {Wdh, Wdx, Wdb};
        for (int s = 0; s < 3; s++)
            sgemm128<<<gW, 256>>>(Wd[s], HYP_, (int64_t)H_ * HYP_,
                                  pWzT + (int64_t)s * 4 * HYP_ * HYP_, HYP_, (int64_t)HYP_ * HYP_,
                                  pWcomp + (int64_t)s * 4 * H_ * HYP_, HYP_, (int64_t)H_ * HYP_,
                                  nullptr, nullptr, 0, HYP_, 0);
    }
    comp_bias<<<24, 256>>>(bzh, Wdh, bzx, Wdx, bdb, pbcomp);

    // ---- parallel (state-independent) phase ----
    sgemm128<<<dim3(HYP_/128, (T_*B_)/128, 1), 256>>>(
        x, DIN_, 0, Wq, DIN_, 0, pq, HYP_, 0, bq, nullptr, 0, DIN_, 0);
    sgemm128<<<dim3(HYP_/128, (B_*L_)/128, 1), 256>>>(
        meta, DM_, 0, Wk, DM_, 0, pk, HYP_, 0, bk, nullptr, 0, DM_, 0);
    attn_kernel<<<T_ * B_, 256>>>(pq, pk, meta, inp, patt);
    sgemm128<<<dim3(HYP_/128, (T_*B_)/128, 1), 256>>>(
        x, DIN_, 0, Wm, DIN_ + DM_ + H_, 0, pmpre, HYP_, 0, bm, nullptr, 0, DIN_, 0);
    sgemm128<<<dim3(HYP_/128, (T_*B_)/128, 1), 256>>>(
        patt, DM_, 0, Wm + DIN_, DIN_ + DM_ + H_, 0, pmpre, HYP_, 0,
        nullptr, pmpre, HYP_, DM_, 0);
    sgemm128<<<dim3((4*H_)/128, (T_*B_)/128, 1), 256>>>(
        x, DIN_, 0, w_x, DIN_, 0, pwx, 4 * H_, 0, nullptr, nullptr, 0, DIN_, 0);

    // ---- sequential scan: 3 launches per step ----
    for (int t = 0; t < T_; t++) {
        sgemm_merged<<<dim3(4, 16), 128>>>(ph, Wm + DIN_ + DM_,
                                           pmpre + (int64_t)t * B_ * HYP_, pmerged);
        sgemm_dwh<<<dim3(64, B_/128), 256>>>(ph, w_h, pmerged, pWcomp, pbcomp, pwh, pD);
        const bool last = (t == T_ - 1);
        lstm_step<<<B_, H_>>>(pD, pwh, pwx + (int64_t)t * B_ * 4 * H_, lng, lnb,
                              ph, pc, out + (int64_t)t * B_ * H_,
                              last ? out + OFF_HT : nullptr,
                              last ? out + OFF_CT : nullptr);
    }
}

// round 6
// speedup vs baseline: 1.6450x; 1.6450x over previous
#include <cuda_runtime.h>
#include <stdint.h>
#include <math.h>

// ---------------- problem constants ----------------
#define T_   128
#define B_   512
#define DIN_ 512
#define H_   512
#define DM_  256
#define HYP_ 256
#define L_   100

// output offsets (floats)
#define OUT_N      ((int64_t)T_*B_*H_)
#define OFF_HT     (OUT_N)
#define OFF_CT     (OFF_HT + (int64_t)B_*H_)
#define OFF_HHAT   (OFF_CT + (int64_t)B_*H_)

// ---------------- scratch (device globals) ----------------
__device__ float g_q   [(size_t)T_*B_*HYP_];
__device__ float g_k   [(size_t)B_*L_*HYP_];
__device__ float g_att [(size_t)T_*B_*DM_];
__device__ float g_mpre[(size_t)T_*B_*HYP_];
__device__ float g_wx  [(size_t)T_*B_*4*H_];
__device__ float g_WzT [3*4*HYP_*HYP_];
__device__ float g_Wcomp[3*4*H_*HYP_];
__device__ float g_bcomp[3*4*H_];
__device__ float g_merged[B_*HYP_];
__device__ float g_D  [(size_t)B_*3*4*H_];
__device__ float g_wh [(size_t)B_*4*H_];
__device__ float g_h  [B_*H_];
__device__ float g_c  [B_*H_];

// ================================================================
//  tf32 tensor-core GEMM:  C[m,n] = sum_k A[m,k] * W[n,k]
//  CTA tile 128x128, k-chunk 16, double buffered.
//  8 warps as (wm 0..1) x (wn 0..3); warp tile 64(m) x 32(n).
//  Fragments stored PRE-PERMUTED in smem: frag loads are LDS.128 / LDS.64.
// ================================================================
__device__ __forceinline__ uint32_t f2tf32(float f) {
    uint32_t u; asm("cvt.rna.tf32.f32 %0, %1;" : "=r"(u) : "f"(f)); return u;
}

__device__ __forceinline__ void mma_tf32(float* c, const uint32_t* a, const uint32_t* b) {
    asm volatile(
        "mma.sync.aligned.m16n8k8.row.col.f32.tf32.tf32.f32 "
        "{%0,%1,%2,%3}, {%4,%5,%6,%7}, {%8,%9}, {%0,%1,%2,%3};"
        : "+f"(c[0]), "+f"(c[1]), "+f"(c[2]), "+f"(c[3])
        : "r"(a[0]), "r"(a[1]), "r"(a[2]), "r"(a[3]), "r"(b[0]), "r"(b[1]));
}

// Stage a 128x16 A tile (rows m, cols k) into permuted fragment layout.
// As[(s*8+i)*128 + t*4 + reg]: s = k/8 slice, i = m16 block, t = lane, reg 0..3.
// Element (rr, k) in an m16xk8 frag: lane = (rr&7)*4 + (k&3), reg = (rr>>3) + 2*(k>>2).
__device__ __forceinline__ void stageA(uint32_t* As, int tid, float4 v0, float4 v1) {
    const int r = tid >> 1, chalf = (tid & 1) << 3;
    const int i = r >> 4, rr = r & 15;
    float v[8] = {v0.x, v0.y, v0.z, v0.w, v1.x, v1.y, v1.z, v1.w};
    #pragma unroll
    for (int cc = 0; cc < 8; cc++) {
        const int c = chalf + cc;
        const int s = c >> 3, k = c & 7;
        const int t   = ((rr & 7) << 2) + (k & 3);
        const int reg = (rr >> 3) + ((k >> 2) << 1);
        As[(((s << 3) + i) << 7) + (t << 2) + reg] = f2tf32(v[cc]);
    }
}

// Stage a 128x16 W tile (rows n, cols k) into B fragment layout.
// Bs[(s*16+j)*64 + t*2 + reg]: j = n8 block.
// Element (n=rr, k) in k8xn8 frag: lane = rr*4 + (k&3), reg = k>>2.
__device__ __forceinline__ void stageB(uint32_t* Bs, int tid, float4 v0, float4 v1) {
    const int r = tid >> 1, chalf = (tid & 1) << 3;
    const int j = r >> 3, rr = r & 7;
    float v[8] = {v0.x, v0.y, v0.z, v0.w, v1.x, v1.y, v1.z, v1.w};
    #pragma unroll
    for (int cc = 0; cc < 8; cc++) {
        const int c = chalf + cc;
        const int s = c >> 3, k = c & 7;
        const int t   = (rr << 2) + (k & 3);
        const int reg = k >> 2;
        Bs[(((s << 4) + j) << 6) + (t << 1) + reg] = f2tf32(v[cc]);
    }
}

__device__ __forceinline__ void tgemm_core(
    const float* __restrict__ A, int lda,
    const float* __restrict__ W, int ldw,
    float* __restrict__ C, int ldc,
    const float* __restrict__ bias,
    const float* __restrict__ addsrc, int ldadd,
    int K, int relu, int64_t m0, int n0,
    uint32_t* As, uint32_t* Bs)
{
    const int tid  = threadIdx.x;
    const int lane = tid & 31, warp = tid >> 5;
    const int wm = warp >> 2, wn = warp & 3;        // wm 0..1, wn 0..3

    const float* Ap = A + (m0 + (tid >> 1)) * (int64_t)lda + ((tid & 1) << 3);
    const float* Wp = W + (int64_t)(n0 + (tid >> 1)) * ldw + ((tid & 1) << 3);

    float acc[4][4][4];
    #pragma unroll
    for (int i = 0; i < 4; i++)
        #pragma unroll
        for (int j = 0; j < 4; j++)
            #pragma unroll
            for (int p = 0; p < 4; p++) acc[i][j][p] = 0.f;

    float4 pa0 = *(const float4*)(Ap);
    float4 pa1 = *(const float4*)(Ap + 4);
    float4 pb0 = *(const float4*)(Wp);
    float4 pb1 = *(const float4*)(Wp + 4);
    stageA(As, tid, pa0, pa1);
    stageB(Bs, tid, pb0, pb1);
    __syncthreads();

    int buf = 0;
    for (int k0 = 0; k0 < K; k0 += 16) {
        const bool more = (k0 + 16) < K;
        if (more) {
            pa0 = *(const float4*)(Ap + k0 + 16);
            pa1 = *(const float4*)(Ap + k0 + 20);
            pb0 = *(const float4*)(Wp + k0 + 16);
            pb1 = *(const float4*)(Wp + k0 + 20);
        }
        const uint32_t* Ab = As + (buf << 11);
        const uint32_t* Bb = Bs + (buf << 11);
        #pragma unroll
        for (int s = 0; s < 2; s++) {
            uint32_t afr[4][4], bfr[4][2];
            #pragma unroll
            for (int mf = 0; mf < 4; mf++) {
                uint4 v = *(const uint4*)&Ab[(((s << 3) + (wm << 2) + mf) << 7) + (lane << 2)];
                afr[mf][0] = v.x; afr[mf][1] = v.y; afr[mf][2] = v.z; afr[mf][3] = v.w;
            }
            #pragma unroll
            for (int nf = 0; nf < 4; nf++) {
                uint2 v = *(const uint2*)&Bb[(((s << 4) + (wn << 2) + nf) << 6) + (lane << 1)];
                bfr[nf][0] = v.x; bfr[nf][1] = v.y;
            }
            #pragma unroll
            for (int mf = 0; mf < 4; mf++)
                #pragma unroll
                for (int nf = 0; nf < 4; nf++)
                    mma_tf32(acc[mf][nf], afr[mf], bfr[nf]);
        }
        if (more) {
            buf ^= 1;
            stageA(As + (buf << 11), tid, pa0, pa1);
            stageB(Bs + (buf << 11), tid, pb0, pb1);
            __syncthreads();
        }
    }

    // epilogue: c0,c1 -> (row, col..col+1); c2,c3 -> (row+8, ...)
    #pragma unroll
    for (int mf = 0; mf < 4; mf++) {
        const int64_t r0 = m0 + (wm << 6) + (mf << 4) + (lane >> 2);
        #pragma unroll
        for (int nf = 0; nf < 4; nf++) {
            const int col = n0 + (wn << 5) + (nf << 3) + ((lane & 3) << 1);
            float v0 = acc[mf][nf][0], v1 = acc[mf][nf][1];
            float v2 = acc[mf][nf][2], v3 = acc[mf][nf][3];
            if (bias) {
                float2 bb = *(const float2*)&bias[col];
                v0 += bb.x; v1 += bb.y; v2 += bb.x; v3 += bb.y;
            }
            if (addsrc) {
                float2 s0 = *(const float2*)&addsrc[r0 * ldadd + col];
                float2 s1 = *(const float2*)&addsrc[(r0 + 8) * ldadd + col];
                v0 += s0.x; v1 += s0.y; v2 += s1.x; v3 += s1.y;
            }
            if (relu) {
                v0 = fmaxf(v0, 0.f); v1 = fmaxf(v1, 0.f);
                v2 = fmaxf(v2, 0.f); v3 = fmaxf(v3, 0.f);
            }
            *(float2*)&C[r0 * ldc + col]       = make_float2(v0, v1);
            *(float2*)&C[(r0 + 8) * ldc + col] = make_float2(v2, v3);
        }
    }
}

__global__ void __launch_bounds__(256)
tgemm(const float* __restrict__ A, int lda,
      const float* __restrict__ W, int ldw,
      float* __restrict__ C, int ldc,
      const float* __restrict__ bias,
      const float* __restrict__ addsrc, int ldadd,
      int K, int relu)
{
    __shared__ uint32_t As[2 * 2048];
    __shared__ uint32_t Bs[2 * 2048];
    tgemm_core(A, lda, W, ldw, C, ldc, bias, addsrc, ldadd, K, relu,
               (int64_t)blockIdx.y * 128, blockIdx.x * 128, As, Bs);
}

// per-step combined: bx<16 -> wh = h @ w_h^T ; else D = merged @ Wcomp^T + bcomp
__global__ void __launch_bounds__(256)
tgemm_dwh(const float* __restrict__ h, const float* __restrict__ w_h,
          const float* __restrict__ merged, const float* __restrict__ Wcomp,
          const float* __restrict__ bcomp,
          float* __restrict__ wh, float* __restrict__ D)
{
    __shared__ uint32_t As[2 * 2048];
    __shared__ uint32_t Bs[2 * 2048];
    const int bx = blockIdx.x;
    const int64_t m0 = (int64_t)blockIdx.y * 128;
    if (bx < 16) {
        tgemm_core(h, H_, w_h, H_, wh, 4*H_, nullptr, nullptr, 0,
                   H_, 0, m0, bx * 128, As, Bs);
    } else {
        tgemm_core(merged, HYP_, Wcomp, HYP_, D, 3*4*H_, bcomp, nullptr, 0,
                   HYP_, 0, m0, (bx - 16) * 128, As, Bs);
    }
}

// ================================================================
//  R3 scalar FFMA2 GEMM (kept for tiny preproc GEMMs only)
// ================================================================
typedef unsigned long long u64;

__device__ __forceinline__ u64 dup2f(float a) {
    u64 r; asm("mov.b64 %0, {%1, %1};" : "=l"(r) : "f"(a)); return r;
}
__device__ __forceinline__ void fma2(u64 &c, u64 a, u64 b) {
    asm("fma.rn.f32x2 %0, %1, %2, %0;" : "+l"(c) : "l"(a), "l"(b));
}
__device__ __forceinline__ void unpk(u64 v, float &lo, float &hi) {
    asm("mov.b64 {%0, %1}, %2;" : "=f"(lo), "=f"(hi) : "l"(v));
}

__global__ void __launch_bounds__(256, 2)
sgemm128(const float* __restrict__ A, int lda, int64_t sA,
         const float* __restrict__ W, int ldw, int64_t sW,
         float* __restrict__ C, int ldc, int64_t sC,
         const float* __restrict__ bias, int K)
{
    __shared__ float As[2][16][128];
    __shared__ float Ws[2][16][128];
    const int bz = blockIdx.z;
    A += bz * sA;  W += bz * sW;  C += bz * sC;
    const int64_t m0 = (int64_t)blockIdx.y * 128;
    const int n0 = blockIdx.x * 128;

    const int tid = threadIdx.x;
    const int lr = tid >> 1;
    const int lk = (tid & 1) << 3;
    const float* Ap = A + (m0 + lr) * (int64_t)lda + lk;
    const float* Wp = W + (int64_t)(n0 + lr) * ldw + lk;
    const int tx = tid & 15, ty = tid >> 4;

    u64 acc[8][4];
    #pragma unroll
    for (int i = 0; i < 8; i++)
        #pragma unroll
        for (int j = 0; j < 4; j++) acc[i][j] = 0ull;

    float4 pa0 = *(const float4*)(Ap);
    float4 pa1 = *(const float4*)(Ap + 4);
    float4 pw0 = *(const float4*)(Wp);
    float4 pw1 = *(const float4*)(Wp + 4);
    As[0][lk+0][lr]=pa0.x; As[0][lk+1][lr]=pa0.y; As[0][lk+2][lr]=pa0.z; As[0][lk+3][lr]=pa0.w;
    As[0][lk+4][lr]=pa1.x; As[0][lk+5][lr]=pa1.y; As[0][lk+6][lr]=pa1.z; As[0][lk+7][lr]=pa1.w;
    Ws[0][lk+0][lr]=pw0.x; Ws[0][lk+1][lr]=pw0.y; Ws[0][lk+2][lr]=pw0.z; Ws[0][lk+3][lr]=pw0.w;
    Ws[0][lk+4][lr]=pw1.x; Ws[0][lk+5][lr]=pw1.y; Ws[0][lk+6][lr]=pw1.z; Ws[0][lk+7][lr]=pw1.w;
    __syncthreads();

    int buf = 0;
    for (int k0 = 0; k0 < K; k0 += 16) {
        const bool more = (k0 + 16) < K;
        if (more) {
            pa0 = *(const float4*)(Ap + k0 + 16);
            pa1 = *(const float4*)(Ap + k0 + 20);
            pw0 = *(const float4*)(Wp + k0 + 16);
            pw1 = *(const float4*)(Wp + k0 + 20);
        }
        #pragma unroll
        for (int kk = 0; kk < 16; kk++) {
            float4 a0 = *(const float4*)&As[buf][kk][ty << 3];
            float4 a1 = *(const float4*)&As[buf][kk][(ty << 3) + 4];
            const u64* bp = (const u64*)&Ws[buf][kk][tx << 3];
            u64 b0 = bp[0], b1 = bp[1], b2 = bp[2], b3 = bp[3];
            float am[8] = {a0.x, a0.y, a0.z, a0.w, a1.x, a1.y, a1.z, a1.w};
            #pragma unroll
            for (int i = 0; i < 8; i++) {
                u64 ad = dup2f(am[i]);
                fma2(acc[i][0], ad, b0);
                fma2(acc[i][1], ad, b1);
                fma2(acc[i][2], ad, b2);
                fma2(acc[i][3], ad, b3);
            }
        }
        if (more) {
            const int nb = buf ^ 1;
            As[nb][lk+0][lr]=pa0.x; As[nb][lk+1][lr]=pa0.y; As[nb][lk+2][lr]=pa0.z; As[nb][lk+3][lr]=pa0.w;
            As[nb][lk+4][lr]=pa1.x; As[nb][lk+5][lr]=pa1.y; As[nb][lk+6][lr]=pa1.z; As[nb][lk+7][lr]=pa1.w;
            Ws[nb][lk+0][lr]=pw0.x; Ws[nb][lk+1][lr]=pw0.y; Ws[nb][lk+2][lr]=pw0.z; Ws[nb][lk+3][lr]=pw0.w;
            Ws[nb][lk+4][lr]=pw1.x; Ws[nb][lk+5][lr]=pw1.y; Ws[nb][lk+6][lr]=pw1.z; Ws[nb][lk+7][lr]=pw1.w;
            __syncthreads();
            buf = nb;
        }
    }

    const int nc = n0 + (tx << 3);
    #pragma unroll
    for (int i = 0; i < 8; i++) {
        const int64_t row = m0 + (ty << 3) + i;
        float r[8];
        #pragma unroll
        for (int p = 0; p < 4; p++) {
            float lo, hi; unpk(acc[i][p], lo, hi);
            r[2*p] = lo; r[2*p+1] = hi;
        }
        if (bias) {
            float4 q0 = *(const float4*)&bias[nc];
            float4 q1 = *(const float4*)&bias[nc + 4];
            r[0]+=q0.x; r[1]+=q0.y; r[2]+=q0.z; r[3]+=q0.w;
            r[4]+=q1.x; r[5]+=q1.y; r[6]+=q1.z; r[7]+=q1.w;
        }
        *(float4*)&C[row * (int64_t)ldc + nc]     = make_float4(r[0], r[1], r[2], r[3]);
        *(float4*)&C[row * (int64_t)ldc + nc + 4] = make_float4(r[4], r[5], r[6], r[7]);
    }
}

// ---------------- small scalar GEMM: merged = relu(mpre + h @ Wm3^T) (R3 exact) ----
__global__ void __launch_bounds__(128)
sgemm_merged(const float* __restrict__ h, const float* __restrict__ Wm3,
             const float* __restrict__ mpre, float* __restrict__ mg)
{
    __shared__ float As[2][16][32];
    __shared__ float Ws[2][16][64];
    const int n0 = blockIdx.x << 6;
    const int m0 = blockIdx.y << 5;
    const int tid = threadIdx.x;
    const int ar = tid >> 2, ak = (tid & 3) << 2;
    const int wr = tid >> 1, wk = (tid & 1) << 3;
    const float* Ap = h + (m0 + ar) * H_ + ak;
    const float* Wp = Wm3 + (int64_t)(n0 + wr) * (DIN_ + DM_ + H_) + wk;
    const int tx = tid & 15, ty = tid >> 4;

    float acc[4][4] = {};
    float4 a  = *(const float4*)(Ap);
    float4 w0 = *(const float4*)(Wp);
    float4 w1 = *(const float4*)(Wp + 4);
    As[0][ak+0][ar]=a.x; As[0][ak+1][ar]=a.y; As[0][ak+2][ar]=a.z; As[0][ak+3][ar]=a.w;
    Ws[0][wk+0][wr]=w0.x; Ws[0][wk+1][wr]=w0.y; Ws[0][wk+2][wr]=w0.z; Ws[0][wk+3][wr]=w0.w;
    Ws[0][wk+4][wr]=w1.x; Ws[0][wk+5][wr]=w1.y; Ws[0][wk+6][wr]=w1.z; Ws[0][wk+7][wr]=w1.w;
    __syncthreads();

    int buf = 0;
    for (int k0 = 0; k0 < H_; k0 += 16) {
        const bool more = (k0 + 16) < H_;
        if (more) {
            a  = *(const float4*)(Ap + k0 + 16);
            w0 = *(const float4*)(Wp + k0 + 16);
            w1 = *(const float4*)(Wp + k0 + 20);
        }
        #pragma unroll
        for (int kk = 0; kk < 16; kk++) {
            float4 av = *(const float4*)&As[buf][kk][ty << 2];
            float4 wv = *(const float4*)&Ws[buf][kk][tx << 2];
            float am[4] = {av.x, av.y, av.z, av.w};
            float wn[4] = {wv.x, wv.y, wv.z, wv.w};
            #pragma unroll
            for (int i = 0; i < 4; i++)
                #pragma unroll
                for (int j = 0; j < 4; j++)
                    acc[i][j] += am[i] * wn[j];
        }
        if (more) {
            const int nb = buf ^ 1;
            As[nb][ak+0][ar]=a.x; As[nb][ak+1][ar]=a.y; As[nb][ak+2][ar]=a.z; As[nb][ak+3][ar]=a.w;
            Ws[nb][wk+0][wr]=w0.x; Ws[nb][wk+1][wr]=w0.y; Ws[nb][wk+2][wr]=w0.z; Ws[nb][wk+3][wr]=w0.w;
            Ws[nb][wk+4][wr]=w1.x; Ws[nb][wk+5][wr]=w1.y; Ws[nb][wk+6][wr]=w1.z; Ws[nb][wk+7][wr]=w1.w;
            __syncthreads();
            buf = nb;
        }
    }
    const int nc = n0 + (tx << 2);
    #pragma unroll
    for (int i = 0; i < 4; i++) {
        const int row = m0 + (ty << 2) + i;
        float4 s = *(const float4*)&mpre[row * HYP_ + nc];
        float4 r;
        r.x = fmaxf(acc[i][0] + s.x, 0.f);
        r.y = fmaxf(acc[i][1] + s.y, 0.f);
        r.z = fmaxf(acc[i][2] + s.z, 0.f);
        r.w = fmaxf(acc[i][3] + s.w, 0.f);
        *(float4*)&mg[row * HYP_ + nc] = r;
    }
}

// ---------------- fused attention ----------------
__global__ void __launch_bounds__(256)
attn_kernel(const float* __restrict__ q, const float* __restrict__ k,
            const float* __restrict__ meta, const int* __restrict__ inp,
            float* __restrict__ att)
{
    const int tb = blockIdx.x;
    const int b  = tb & (B_ - 1);
    const int tid = threadIdx.x;
    __shared__ float qs[HYP_];
    __shared__ float sc[128];

    qs[tid] = q[(int64_t)tb * HYP_ + tid] * 0.0625f;
    __syncthreads();

    const int lane = tid & 31, wrp = tid >> 5;
    for (int l = wrp; l < L_; l += 8) {
        const float* kp = k + ((int64_t)b * L_ + l) * HYP_;
        float s = 0.f;
        #pragma unroll
        for (int e = 0; e < HYP_ / 32; e++)
            s += qs[lane + 32 * e] * kp[lane + 32 * e];
        #pragma unroll
        for (int o = 16; o; o >>= 1) s += __shfl_xor_sync(0xffffffffu, s, o);
        if (lane == 0) sc[l] = (inp[b * L_ + l] == 0) ? -1e9f : s;
    }
    __syncthreads();

    if (tid < 32) {
        float v[4]; float m = -3.0e38f;
        #pragma unroll
        for (int j = 0; j < 4; j++) {
            int l = tid + 32 * j;
            v[j] = (l < L_) ? sc[l] : -3.0e38f;
            m = fmaxf(m, v[j]);
        }
        #pragma unroll
        for (int o = 16; o; o >>= 1) m = fmaxf(m, __shfl_xor_sync(0xffffffffu, m, o));
        float s = 0.f;
        #pragma unroll
        for (int j = 0; j < 4; j++) { v[j] = expf(v[j] - m); s += v[j]; }
        #pragma unroll
        for (int o = 16; o; o >>= 1) s += __shfl_xor_sync(0xffffffffu, s, o);
        const float inv = 1.0f / s;
        #pragma unroll
        for (int j = 0; j < 4; j++) {
            int l = tid + 32 * j;
            if (l < L_) sc[l] = v[j] * inv;
        }
    }
    __syncthreads();

    float acc = 0.f;
    const float* mp = meta + (int64_t)b * L_ * DM_ + tid;
    #pragma unroll 4
    for (int l = 0; l < L_; l++) acc += sc[l] * mp[(int64_t)l * DM_];
    att[(int64_t)tb * DM_ + tid] = acc;
}

// ---------------- weight preprocessing ----------------
__global__ void transpose_wz(const float* __restrict__ Wzh, const float* __restrict__ Wzx,
                             const float* __restrict__ Wzb, float* __restrict__ WzT)
{
    int idx = blockIdx.x * 256 + threadIdx.x;
    int s  = idx / (4 * HYP_ * HYP_);
    int r  = idx % (4 * HYP_ * HYP_);
    int kk = r / (HYP_ * HYP_);
    int r2 = r % (HYP_ * HYP_);
    int z  = r2 / HYP_;
    int z2 = r2 % HYP_;
    const float* Wz = (s == 0) ? Wzh : ((s == 1) ? Wzx : Wzb);
    WzT[idx] = Wz[(kk * HYP_ + z2) * HYP_ + z];
}

__global__ void comp_bias(const float* __restrict__ bzh, const float* __restrict__ Wdh,
                          const float* __restrict__ bzx, const float* __restrict__ Wdx,
                          const float* __restrict__ bdb, float* __restrict__ bcomp)
{
    int n = blockIdx.x * 256 + threadIdx.x;
    if (n < 2048) {
        int kk = n >> 9;
        float s = 0.f;
        for (int z = 0; z < HYP_; z++) s += bzh[kk * HYP_ + z] * Wdh[n * HYP_ + z];
        bcomp[n] = s;
    } else if (n < 4096) {
        int m = n - 2048; int kk = m >> 9;
        float s = 0.f;
        for (int z = 0; z < HYP_; z++) s += bzx[kk * HYP_ + z] * Wdx[m * HYP_ + z];
        bcomp[n] = s;
    } else {
        bcomp[n] = bdb[n - 4096];
    }
}

__global__ void init_zero(float* __restrict__ h, float* __restrict__ c,
                          float* __restrict__ tail)
{
    int i = blockIdx.x * 256 + threadIdx.x;
    h[i] = 0.f; c[i] = 0.f; tail[i] = 0.f;
}

// ---------------- fused elementwise + LayerNorm + LSTM cell ----------------
__global__ void __launch_bounds__(512)
lstm_step(const float* __restrict__ D, const float* __restrict__ wh,
          const float* __restrict__ wx, const float* __restrict__ lng,
          const float* __restrict__ lnb, float* __restrict__ h,
          float* __restrict__ c, float* __restrict__ out,
          float* __restrict__ hT, float* __restrict__ cT)
{
    const int b  = blockIdx.x;
    const int hh = threadIdx.x;
    const int lane = hh & 31, wrp = hh >> 5;
    __shared__ float red[4][16];
    __shared__ float mu_s[4], iv_s[4];

    float y[4];
    #pragma unroll
    for (int k = 0; k < 4; k++) {
        const int idx = k * H_ + hh;
        const int64_t base = (int64_t)b * 6144;
        float dh = D[base + idx];
        float dx = D[base + 2048 + idx];
        float db = D[base + 4096 + idx];
        y[k] = dh * wh[(int64_t)b * 2048 + idx] + dx * wx[(int64_t)b * 2048 + idx] + db;
    }
    #pragma unroll
    for (int k = 0; k < 4; k++) {
        float s = y[k];
        #pragma unroll
        for (int o = 16; o; o >>= 1) s += __shfl_xor_sync(0xffffffffu, s, o);
        if (lane == 0) red[k][wrp] = s;
    }
    __syncthreads();
    if (hh < 4) {
        float s = 0.f;
        #pragma unroll
        for (int w = 0; w < 16; w++) s += red[hh][w];
        mu_s[hh] = s * (1.0f / H_);
    }
    __syncthreads();
    const float mu[4] = {mu_s[0], mu_s[1], mu_s[2], mu_s[3]};
    #pragma unroll
    for (int k = 0; k < 4; k++) {
        float d = y[k] - mu[k];
        float s = d * d;
        #pragma unroll
        for (int o = 16; o; o >>= 1) s += __shfl_xor_sync(0xffffffffu, s, o);
        if (lane == 0) red[k][wrp] = s;
    }
    __syncthreads();
    if (hh < 4) {
        float s = 0.f;
        #pragma unroll
        for (int w = 0; w < 16; w++) s += red[hh][w];
        iv_s[hh] = rsqrtf(s * (1.0f / H_) + 1e-5f);
    }
    __syncthreads();

    float yn[4];
    #pragma unroll
    for (int k = 0; k < 4; k++)
        yn[k] = (y[k] - mu[k]) * iv_s[k] * lng[k * H_ + hh] + lnb[k * H_ + hh];

    const float ig = 1.f / (1.f + expf(-yn[0]));
    const float fg = 1.f / (1.f + expf(-yn[1]));
    const float gg = tanhf(yn[2]);
    const float og = 1.f / (1.f + expf(-yn[3]));

    const int64_t bi = (int64_t)b * H_ + hh;
    const float cn = fg * c[bi] + ig * gg;
    const float hn = og * tanhf(cn);
    c[bi] = cn;  h[bi] = hn;  out[bi] = hn;
    if (hT) { hT[bi] = hn; cT[bi] = cn; }
}

// ---------------- host driver ----------------
extern "C" void kernel_launch(void* const* d_in, const int* in_sizes, int n_in,
                              void* d_out, int out_size)
{
    const float* x    = (const float*)d_in[0];
    const float* meta = (const float*)d_in[1];
    const int*   inp  = (const int*)  d_in[2];
    const float* Wq   = (const float*)d_in[3];
    const float* bq   = (const float*)d_in[4];
    const float* Wk   = (const float*)d_in[5];
    const float* bk   = (const float*)d_in[6];
    const float* Wm   = (const float*)d_in[7];
    const float* bm   = (const float*)d_in[8];
    const float* Wzh  = (const float*)d_in[9];
    const float* bzh  = (const float*)d_in[10];
    const float* Wzx  = (const float*)d_in[11];
    const float* bzx  = (const float*)d_in[12];
    const float* Wzb  = (const float*)d_in[13];
    const float* Wdh  = (const float*)d_in[14];
    const float* Wdx  = (const float*)d_in[15];
    const float* Wdb  = (const float*)d_in[16];
    const float* bdb  = (const float*)d_in[17];
    const float* w_h  = (const float*)d_in[18];
    const float* w_x  = (const float*)d_in[19];
    const float* lng  = (const float*)d_in[20];
    const float* lnb  = (const float*)d_in[21];
    float* out = (float*)d_out;

    float *pq, *pk, *patt, *pmpre, *pwx, *pWzT, *pWcomp, *pbcomp,
          *pmerged, *pD, *pwh, *ph, *pc;
    cudaGetSymbolAddress((void**)&pq,     g_q);
    cudaGetSymbolAddress((void**)&pk,     g_k);
    cudaGetSymbolAddress((void**)&patt,   g_att);
    cudaGetSymbolAddress((void**)&pmpre,  g_mpre);
    cudaGetSymbolAddress((void**)&pwx,    g_wx);
    cudaGetSymbolAddress((void**)&pWzT,   g_WzT);
    cudaGetSymbolAddress((void**)&pWcomp, g_Wcomp);
    cudaGetSymbolAddress((void**)&pbcomp, g_bcomp);
    cudaGetSymbolAddress((void**)&pmerged,g_merged);
    cudaGetSymbolAddress((void**)&pD,     g_D);
    cudaGetSymbolAddress((void**)&pwh,    g_wh);
    cudaGetSymbolAddress((void**)&ph,     g_h);
    cudaGetSymbolAddress((void**)&pc,     g_c);

    init_zero<<<1024, 256>>>(ph, pc, out + OFF_HHAT);

    // ---- weight preprocessing (fp32 exact) ----
    transpose_wz<<<3072, 256>>>(Wzh, Wzx, Wzb, pWzT);
    {
        dim3 gW(HYP_ / 128, H_ / 128, 4);
        const float* Wd[3] = {Wdh, Wdx, Wdb};
        for (int s = 0; s < 3; s++)
            sgemm128<<<gW, 256>>>(Wd[s], HYP_, (int64_t)H_ * HYP_,
                                  pWzT + (int64_t)s * 4 * HYP_ * HYP_, HYP_, (int64_t)HYP_ * HYP_,
                                  pWcomp + (int64_t)s * 4 * H_ * HYP_, HYP_, (int64_t)H_ * HYP_,
                                  nullptr, HYP_);
    }
    comp_bias<<<24, 256>>>(bzh, Wdh, bzx, Wdx, bdb, pbcomp);

    // ---- parallel (state-independent) phase — tf32 tensor GEMMs ----
    // q = x @ Wq^T + bq
    tgemm<<<dim3(HYP_/128, (T_*B_)/128), 256>>>(
        x, DIN_, Wq, DIN_, pq, HYP_, bq, nullptr, 0, DIN_, 0);
    // k = meta @ Wk^T + bk
    tgemm<<<dim3(HYP_/128, (B_*L_)/128), 256>>>(
        meta, DM_, Wk, DM_, pk, HYP_, bk, nullptr, 0, DM_, 0);
    // attention
    attn_kernel<<<T_ * B_, 256>>>(pq, pk, meta, inp, patt);
    // mergedpre = x @ Wm[:, :512]^T + bm
    tgemm<<<dim3(HYP_/128, (T_*B_)/128), 256>>>(
        x, DIN_, Wm, DIN_ + DM_ + H_, pmpre, HYP_, bm, nullptr, 0, DIN_, 0);
    // mergedpre += attended @ Wm[:, 512:768]^T
    tgemm<<<dim3(HYP_/128, (T_*B_)/128), 256>>>(
        patt, DM_, Wm + DIN_, DIN_ + DM_ + H_, pmpre, HYP_, nullptr, pmpre, HYP_, DM_, 0);
    // wx_all = x @ w_x^T  (T*B, 2048)
    tgemm<<<dim3((4*H_)/128, (T_*B_)/128), 256>>>(
        x, DIN_, w_x, DIN_, pwx, 4*H_, nullptr, nullptr, 0, DIN_, 0);

    // ---- sequential scan: 3 launches per step ----
    for (int t = 0; t < T_; t++) {
        // merged = relu(mergedpre[t] + h @ Wm[:, 768:]^T)   (scalar, 64 blocks)
        sgemm_merged<<<dim3(4, 16), 128>>>(ph, Wm + DIN_ + DM_,
                                           pmpre + (int64_t)t * B_ * HYP_, pmerged);
        // wh = h @ w_h^T | D = merged @ Wcomp^T + bcomp   (tf32 tensor)
        tgemm_dwh<<<dim3(64, B_/128), 256>>>(ph, w_h, pmerged, pWcomp, pbcomp, pwh, pD);
        // elementwise + LN + LSTM cell
        const bool last = (t == T_ - 1);
        lstm_step<<<B_, H_>>>(pD, pwh, pwx + (int64_t)t * B_ * 4 * H_, lng, lnb,
                              ph, pc, out + (int64_t)t * B_ * H_,
                              last ? out + OFF_HT : nullptr,
                              last ? out + OFF_CT : nullptr);
    }
}

// round 7
// speedup vs baseline: 1.6451x; 1.0001x over previous
#include <cuda_runtime.h>
#include <stdint.h>
#include <math.h>

// ---------------- problem constants ----------------
#define T_   128
#define B_   512
#define DIN_ 512
#define H_   512
#define DM_  256
#define HYP_ 256
#define L_   100

// output offsets (floats)
#define OUT_N      ((int64_t)T_*B_*H_)
#define OFF_HT     (OUT_N)
#define OFF_CT     (OFF_HT + (int64_t)B_*H_)
#define OFF_HHAT   (OFF_CT + (int64_t)B_*H_)

// ---------------- scratch (device globals) ----------------
__device__ float g_q   [(size_t)T_*B_*HYP_];
__device__ float g_k   [(size_t)B_*L_*HYP_];
__device__ float g_att [(size_t)T_*B_*DM_];
__device__ float g_mpre[(size_t)T_*B_*HYP_];
__device__ float g_wx  [(size_t)T_*B_*4*H_];
__device__ float g_WzT [3*4*HYP_*HYP_];
__device__ float g_Wcomp[3*4*H_*HYP_];
__device__ float g_bcomp[3*4*H_];
__device__ float g_merged[B_*HYP_];
__device__ float g_D  [(size_t)B_*3*4*H_];
__device__ float g_wh [(size_t)B_*4*H_];
__device__ float g_h  [B_*H_];
__device__ float g_c  [B_*H_];

// ================================================================
//  tf32 tensor-core GEMM:  C[m,n] = sum_k A[m,k] * W[n,k]
//  CTA tile 128x128, k-chunk 16, double buffered.
//  8 warps as (wm 0..1) x (wn 0..3); warp tile 64(m) x 32(n).
//  Fragments stored PRE-PERMUTED in smem: frag loads are LDS.128 / LDS.64.
// ================================================================
__device__ __forceinline__ uint32_t f2tf32(float f) {
    uint32_t u; asm("cvt.rna.tf32.f32 %0, %1;" : "=r"(u) : "f"(f)); return u;
}

__device__ __forceinline__ void mma_tf32(float* c, const uint32_t* a, const uint32_t* b) {
    asm volatile(
        "mma.sync.aligned.m16n8k8.row.col.f32.tf32.tf32.f32 "
        "{%0,%1,%2,%3}, {%4,%5,%6,%7}, {%8,%9}, {%0,%1,%2,%3};"
        : "+f"(c[0]), "+f"(c[1]), "+f"(c[2]), "+f"(c[3])
        : "r"(a[0]), "r"(a[1]), "r"(a[2]), "r"(a[3]), "r"(b[0]), "r"(b[1]));
}

// Stage a 128x16 A tile (rows m, cols k) into permuted fragment layout.
// As[(s*8+i)*128 + t*4 + reg]: s = k/8 slice, i = m16 block, t = lane, reg 0..3.
// Element (rr, k) in an m16xk8 frag: lane = (rr&7)*4 + (k&3), reg = (rr>>3) + 2*(k>>2).
__device__ __forceinline__ void stageA(uint32_t* As, int tid, float4 v0, float4 v1) {
    const int r = tid >> 1, chalf = (tid & 1) << 3;
    const int i = r >> 4, rr = r & 15;
    float v[8] = {v0.x, v0.y, v0.z, v0.w, v1.x, v1.y, v1.z, v1.w};
    #pragma unroll
    for (int cc = 0; cc < 8; cc++) {
        const int c = chalf + cc;
        const int s = c >> 3, k = c & 7;
        const int t   = ((rr & 7) << 2) + (k & 3);
        const int reg = (rr >> 3) + ((k >> 2) << 1);
        As[(((s << 3) + i) << 7) + (t << 2) + reg] = f2tf32(v[cc]);
    }
}

// Stage a 128x16 W tile (rows n, cols k) into B fragment layout.
// Bs[(s*16+j)*64 + t*2 + reg]: j = n8 block.
// Element (n=rr, k) in k8xn8 frag: lane = rr*4 + (k&3), reg = k>>2.
__device__ __forceinline__ void stageB(uint32_t* Bs, int tid, float4 v0, float4 v1) {
    const int r = tid >> 1, chalf = (tid & 1) << 3;
    const int j = r >> 3, rr = r & 7;
    float v[8] = {v0.x, v0.y, v0.z, v0.w, v1.x, v1.y, v1.z, v1.w};
    #pragma unroll
    for (int cc = 0; cc < 8; cc++) {
        const int c = chalf + cc;
        const int s = c >> 3, k = c & 7;
        const int t   = (rr << 2) + (k & 3);
        const int reg = k >> 2;
        Bs[(((s << 4) + j) << 6) + (t << 1) + reg] = f2tf32(v[cc]);
    }
}

__device__ __forceinline__ void tgemm_core(
    const float* __restrict__ A, int lda,
    const float* __restrict__ W, int ldw,
    float* __restrict__ C, int ldc,
    const float* __restrict__ bias,
    const float* __restrict__ addsrc, int ldadd,
    int K, int relu, int64_t m0, int n0,
    uint32_t* As, uint32_t* Bs)
{
    const int tid  = threadIdx.x;
    const int lane = tid & 31, warp = tid >> 5;
    const int wm = warp >> 2, wn = warp & 3;        // wm 0..1, wn 0..3

    const float* Ap = A + (m0 + (tid >> 1)) * (int64_t)lda + ((tid & 1) << 3);
    const float* Wp = W + (int64_t)(n0 + (tid >> 1)) * ldw + ((tid & 1) << 3);

    float acc[4][4][4];
    #pragma unroll
    for (int i = 0; i < 4; i++)
        #pragma unroll
        for (int j = 0; j < 4; j++)
            #pragma unroll
            for (int p = 0; p < 4; p++) acc[i][j][p] = 0.f;

    float4 pa0 = *(const float4*)(Ap);
    float4 pa1 = *(const float4*)(Ap + 4);
    float4 pb0 = *(const float4*)(Wp);
    float4 pb1 = *(const float4*)(Wp + 4);
    stageA(As, tid, pa0, pa1);
    stageB(Bs, tid, pb0, pb1);
    __syncthreads();

    int buf = 0;
    for (int k0 = 0; k0 < K; k0 += 16) {
        const bool more = (k0 + 16) < K;
        if (more) {
            pa0 = *(const float4*)(Ap + k0 + 16);
            pa1 = *(const float4*)(Ap + k0 + 20);
            pb0 = *(const float4*)(Wp + k0 + 16);
            pb1 = *(const float4*)(Wp + k0 + 20);
        }
        const uint32_t* Ab = As + (buf << 11);
        const uint32_t* Bb = Bs + (buf << 11);
        #pragma unroll
        for (int s = 0; s < 2; s++) {
            uint32_t afr[4][4], bfr[4][2];
            #pragma unroll
            for (int mf = 0; mf < 4; mf++) {
                uint4 v = *(const uint4*)&Ab[(((s << 3) + (wm << 2) + mf) << 7) + (lane << 2)];
                afr[mf][0] = v.x; afr[mf][1] = v.y; afr[mf][2] = v.z; afr[mf][3] = v.w;
            }
            #pragma unroll
            for (int nf = 0; nf < 4; nf++) {
                uint2 v = *(const uint2*)&Bb[(((s << 4) + (wn << 2) + nf) << 6) + (lane << 1)];
                bfr[nf][0] = v.x; bfr[nf][1] = v.y;
            }
            #pragma unroll
            for (int mf = 0; mf < 4; mf++)
                #pragma unroll
                for (int nf = 0; nf < 4; nf++)
                    mma_tf32(acc[mf][nf], afr[mf], bfr[nf]);
        }
        if (more) {
            buf ^= 1;
            stageA(As + (buf << 11), tid, pa0, pa1);
            stageB(Bs + (buf << 11), tid, pb0, pb1);
            __syncthreads();
        }
    }

    // epilogue: c0,c1 -> (row, col..col+1); c2,c3 -> (row+8, ...)
    #pragma unroll
    for (int mf = 0; mf < 4; mf++) {
        const int64_t r0 = m0 + (wm << 6) + (mf << 4) + (lane >> 2);
        #pragma unroll
        for (int nf = 0; nf < 4; nf++) {
            const int col = n0 + (wn << 5) + (nf << 3) + ((lane & 3) << 1);
            float v0 = acc[mf][nf][0], v1 = acc[mf][nf][1];
            float v2 = acc[mf][nf][2], v3 = acc[mf][nf][3];
            if (bias) {
                float2 bb = *(const float2*)&bias[col];
                v0 += bb.x; v1 += bb.y; v2 += bb.x; v3 += bb.y;
            }
            if (addsrc) {
                float2 s0 = *(const float2*)&addsrc[r0 * ldadd + col];
                float2 s1 = *(const float2*)&addsrc[(r0 + 8) * ldadd + col];
                v0 += s0.x; v1 += s0.y; v2 += s1.x; v3 += s1.y;
            }
            if (relu) {
                v0 = fmaxf(v0, 0.f); v1 = fmaxf(v1, 0.f);
                v2 = fmaxf(v2, 0.f); v3 = fmaxf(v3, 0.f);
            }
            *(float2*)&C[r0 * ldc + col]       = make_float2(v0, v1);
            *(float2*)&C[(r0 + 8) * ldc + col] = make_float2(v2, v3);
        }
    }
}

__global__ void __launch_bounds__(256)
tgemm(const float* __restrict__ A, int lda,
      const float* __restrict__ W, int ldw,
      float* __restrict__ C, int ldc,
      const float* __restrict__ bias,
      const float* __restrict__ addsrc, int ldadd,
      int K, int relu)
{
    __shared__ uint32_t As[2 * 2048];
    __shared__ uint32_t Bs[2 * 2048];
    tgemm_core(A, lda, W, ldw, C, ldc, bias, addsrc, ldadd, K, relu,
               (int64_t)blockIdx.y * 128, blockIdx.x * 128, As, Bs);
}

// per-step combined: bx<16 -> wh = h @ w_h^T ; else D = merged @ Wcomp^T + bcomp
__global__ void __launch_bounds__(256)
tgemm_dwh(const float* __restrict__ h, const float* __restrict__ w_h,
          const float* __restrict__ merged, const float* __restrict__ Wcomp,
          const float* __restrict__ bcomp,
          float* __restrict__ wh, float* __restrict__ D)
{
    __shared__ uint32_t As[2 * 2048];
    __shared__ uint32_t Bs[2 * 2048];
    const int bx = blockIdx.x;
    const int64_t m0 = (int64_t)blockIdx.y * 128;
    if (bx < 16) {
        tgemm_core(h, H_, w_h, H_, wh, 4*H_, nullptr, nullptr, 0,
                   H_, 0, m0, bx * 128, As, Bs);
    } else {
        tgemm_core(merged, HYP_, Wcomp, HYP_, D, 3*4*H_, bcomp, nullptr, 0,
                   HYP_, 0, m0, (bx - 16) * 128, As, Bs);
    }
}

// ================================================================
//  R3 scalar FFMA2 GEMM (kept for tiny preproc GEMMs only)
// ================================================================
typedef unsigned long long u64;

__device__ __forceinline__ u64 dup2f(float a) {
    u64 r; asm("mov.b64 %0, {%1, %1};" : "=l"(r) : "f"(a)); return r;
}
__device__ __forceinline__ void fma2(u64 &c, u64 a, u64 b) {
    asm("fma.rn.f32x2 %0, %1, %2, %0;" : "+l"(c) : "l"(a), "l"(b));
}
__device__ __forceinline__ void unpk(u64 v, float &lo, float &hi) {
    asm("mov.b64 {%0, %1}, %2;" : "=f"(lo), "=f"(hi) : "l"(v));
}

__global__ void __launch_bounds__(256, 2)
sgemm128(const float* __restrict__ A, int lda, int64_t sA,
         const float* __restrict__ W, int ldw, int64_t sW,
         float* __restrict__ C, int ldc, int64_t sC,
         const float* __restrict__ bias, int K)
{
    __shared__ float As[2][16][128];
    __shared__ float Ws[2][16][128];
    const int bz = blockIdx.z;
    A += bz * sA;  W += bz * sW;  C += bz * sC;
    const int64_t m0 = (int64_t)blockIdx.y * 128;
    const int n0 = blockIdx.x * 128;

    const int tid = threadIdx.x;
    const int lr = tid >> 1;
    const int lk = (tid & 1) << 3;
    const float* Ap = A + (m0 + lr) * (int64_t)lda + lk;
    const float* Wp = W + (int64_t)(n0 + lr) * ldw + lk;
    const int tx = tid & 15, ty = tid >> 4;

    u64 acc[8][4];
    #pragma unroll
    for (int i = 0; i < 8; i++)
        #pragma unroll
        for (int j = 0; j < 4; j++) acc[i][j] = 0ull;

    float4 pa0 = *(const float4*)(Ap);
    float4 pa1 = *(const float4*)(Ap + 4);
    float4 pw0 = *(const float4*)(Wp);
    float4 pw1 = *(const float4*)(Wp + 4);
    As[0][lk+0][lr]=pa0.x; As[0][lk+1][lr]=pa0.y; As[0][lk+2][lr]=pa0.z; As[0][lk+3][lr]=pa0.w;
    As[0][lk+4][lr]=pa1.x; As[0][lk+5][lr]=pa1.y; As[0][lk+6][lr]=pa1.z; As[0][lk+7][lr]=pa1.w;
    Ws[0][lk+0][lr]=pw0.x; Ws[0][lk+1][lr]=pw0.y; Ws[0][lk+2][lr]=pw0.z; Ws[0][lk+3][lr]=pw0.w;
    Ws[0][lk+4][lr]=pw1.x; Ws[0][lk+5][lr]=pw1.y; Ws[0][lk+6][lr]=pw1.z; Ws[0][lk+7][lr]=pw1.w;
    __syncthreads();

    int buf = 0;
    for (int k0 = 0; k0 < K; k0 += 16) {
        const bool more = (k0 + 16) < K;
        if (more) {
            pa0 = *(const float4*)(Ap + k0 + 16);
            pa1 = *(const float4*)(Ap + k0 + 20);
            pw0 = *(const float4*)(Wp + k0 + 16);
            pw1 = *(const float4*)(Wp + k0 + 20);
        }
        #pragma unroll
        for (int kk = 0; kk < 16; kk++) {
            float4 a0 = *(const float4*)&As[buf][kk][ty << 3];
            float4 a1 = *(const float4*)&As[buf][kk][(ty << 3) + 4];
            const u64* bp = (const u64*)&Ws[buf][kk][tx << 3];
            u64 b0 = bp[0], b1 = bp[1], b2 = bp[2], b3 = bp[3];
            float am[8] = {a0.x, a0.y, a0.z, a0.w, a1.x, a1.y, a1.z, a1.w};
            #pragma unroll
            for (int i = 0; i < 8; i++) {
                u64 ad = dup2f(am[i]);
                fma2(acc[i][0], ad, b0);
                fma2(acc[i][1], ad, b1);
                fma2(acc[i][2], ad, b2);
                fma2(acc[i][3], ad, b3);
            }
        }
        if (more) {
            const int nb = buf ^ 1;
            As[nb][lk+0][lr]=pa0.x; As[nb][lk+1][lr]=pa0.y; As[nb][lk+2][lr]=pa0.z; As[nb][lk+3][lr]=pa0.w;
            As[nb][lk+4][lr]=pa1.x; As[nb][lk+5][lr]=pa1.y; As[nb][lk+6][lr]=pa1.z; As[nb][lk+7][lr]=pa1.w;
            Ws[nb][lk+0][lr]=pw0.x; Ws[nb][lk+1][lr]=pw0.y; Ws[nb][lk+2][lr]=pw0.z; Ws[nb][lk+3][lr]=pw0.w;
            Ws[nb][lk+4][lr]=pw1.x; Ws[nb][lk+5][lr]=pw1.y; Ws[nb][lk+6][lr]=pw1.z; Ws[nb][lk+7][lr]=pw1.w;
            __syncthreads();
            buf = nb;
        }
    }

    const int nc = n0 + (tx << 3);
    #pragma unroll
    for (int i = 0; i < 8; i++) {
        const int64_t row = m0 + (ty << 3) + i;
        float r[8];
        #pragma unroll
        for (int p = 0; p < 4; p++) {
            float lo, hi; unpk(acc[i][p], lo, hi);
            r[2*p] = lo; r[2*p+1] = hi;
        }
        if (bias) {
            float4 q0 = *(const float4*)&bias[nc];
            float4 q1 = *(const float4*)&bias[nc + 4];
            r[0]+=q0.x; r[1]+=q0.y; r[2]+=q0.z; r[3]+=q0.w;
            r[4]+=q1.x; r[5]+=q1.y; r[6]+=q1.z; r[7]+=q1.w;
        }
        *(float4*)&C[row * (int64_t)ldc + nc]     = make_float4(r[0], r[1], r[2], r[3]);
        *(float4*)&C[row * (int64_t)ldc + nc + 4] = make_float4(r[4], r[5], r[6], r[7]);
    }
}

// ---------------- small scalar GEMM: merged = relu(mpre + h @ Wm3^T) (R3 exact) ----
__global__ void __launch_bounds__(128)
sgemm_merged(const float* __restrict__ h, const float* __restrict__ Wm3,
             const float* __restrict__ mpre, float* __restrict__ mg)
{
    __shared__ float As[2][16][32];
    __shared__ float Ws[2][16][64];
    const int n0 = blockIdx.x << 6;
    const int m0 = blockIdx.y << 5;
    const int tid = threadIdx.x;
    const int ar = tid >> 2, ak = (tid & 3) << 2;
    const int wr = tid >> 1, wk = (tid & 1) << 3;
    const float* Ap = h + (m0 + ar) * H_ + ak;
    const float* Wp = Wm3 + (int64_t)(n0 + wr) * (DIN_ + DM_ + H_) + wk;
    const int tx = tid & 15, ty = tid >> 4;

    float acc[4][4] = {};
    float4 a  = *(const float4*)(Ap);
    float4 w0 = *(const float4*)(Wp);
    float4 w1 = *(const float4*)(Wp + 4);
    As[0][ak+0][ar]=a.x; As[0][ak+1][ar]=a.y; As[0][ak+2][ar]=a.z; As[0][ak+3][ar]=a.w;
    Ws[0][wk+0][wr]=w0.x; Ws[0][wk+1][wr]=w0.y; Ws[0][wk+2][wr]=w0.z; Ws[0][wk+3][wr]=w0.w;
    Ws[0][wk+4][wr]=w1.x; Ws[0][wk+5][wr]=w1.y; Ws[0][wk+6][wr]=w1.z; Ws[0][wk+7][wr]=w1.w;
    __syncthreads();

    int buf = 0;
    for (int k0 = 0; k0 < H_; k0 += 16) {
        const bool more = (k0 + 16) < H_;
        if (more) {
            a  = *(const float4*)(Ap + k0 + 16);
            w0 = *(const float4*)(Wp + k0 + 16);
            w1 = *(const float4*)(Wp + k0 + 20);
        }
        #pragma unroll
        for (int kk = 0; kk < 16; kk++) {
            float4 av = *(const float4*)&As[buf][kk][ty << 2];
            float4 wv = *(const float4*)&Ws[buf][kk][tx << 2];
            float am[4] = {av.x, av.y, av.z, av.w};
            float wn[4] = {wv.x, wv.y, wv.z, wv.w};
            #pragma unroll
            for (int i = 0; i < 4; i++)
                #pragma unroll
                for (int j = 0; j < 4; j++)
                    acc[i][j] += am[i] * wn[j];
        }
        if (more) {
            const int nb = buf ^ 1;
            As[nb][ak+0][ar]=a.x; As[nb][ak+1][ar]=a.y; As[nb][ak+2][ar]=a.z; As[nb][ak+3][ar]=a.w;
            Ws[nb][wk+0][wr]=w0.x; Ws[nb][wk+1][wr]=w0.y; Ws[nb][wk+2][wr]=w0.z; Ws[nb][wk+3][wr]=w0.w;
            Ws[nb][wk+4][wr]=w1.x; Ws[nb][wk+5][wr]=w1.y; Ws[nb][wk+6][wr]=w1.z; Ws[nb][wk+7][wr]=w1.w;
            __syncthreads();
            buf = nb;
        }
    }
    const int nc = n0 + (tx << 2);
    #pragma unroll
    for (int i = 0; i < 4; i++) {
        const int row = m0 + (ty << 2) + i;
        float4 s = *(const float4*)&mpre[row * HYP_ + nc];
        float4 r;
        r.x = fmaxf(acc[i][0] + s.x, 0.f);
        r.y = fmaxf(acc[i][1] + s.y, 0.f);
        r.z = fmaxf(acc[i][2] + s.z, 0.f);
        r.w = fmaxf(acc[i][3] + s.w, 0.f);
        *(float4*)&mg[row * HYP_ + nc] = r;
    }
}

// ---------------- fused attention ----------------
__global__ void __launch_bounds__(256)
attn_kernel(const float* __restrict__ q, const float* __restrict__ k,
            const float* __restrict__ meta, const int* __restrict__ inp,
            float* __restrict__ att)
{
    const int tb = blockIdx.x;
    const int b  = tb & (B_ - 1);
    const int tid = threadIdx.x;
    __shared__ float qs[HYP_];
    __shared__ float sc[128];

    qs[tid] = q[(int64_t)tb * HYP_ + tid] * 0.0625f;
    __syncthreads();

    const int lane = tid & 31, wrp = tid >> 5;
    for (int l = wrp; l < L_; l += 8) {
        const float* kp = k + ((int64_t)b * L_ + l) * HYP_;
        float s = 0.f;
        #pragma unroll
        for (int e = 0; e < HYP_ / 32; e++)
            s += qs[lane + 32 * e] * kp[lane + 32 * e];
        #pragma unroll
        for (int o = 16; o; o >>= 1) s += __shfl_xor_sync(0xffffffffu, s, o);
        if (lane == 0) sc[l] = (inp[b * L_ + l] == 0) ? -1e9f : s;
    }
    __syncthreads();

    if (tid < 32) {
        float v[4]; float m = -3.0e38f;
        #pragma unroll
        for (int j = 0; j < 4; j++) {
            int l = tid + 32 * j;
            v[j] = (l < L_) ? sc[l] : -3.0e38f;
            m = fmaxf(m, v[j]);
        }
        #pragma unroll
        for (int o = 16; o; o >>= 1) m = fmaxf(m, __shfl_xor_sync(0xffffffffu, m, o));
        float s = 0.f;
        #pragma unroll
        for (int j = 0; j < 4; j++) { v[j] = expf(v[j] - m); s += v[j]; }
        #pragma unroll
        for (int o = 16; o; o >>= 1) s += __shfl_xor_sync(0xffffffffu, s, o);
        const float inv = 1.0f / s;
        #pragma unroll
        for (int j = 0; j < 4; j++) {
            int l = tid + 32 * j;
            if (l < L_) sc[l] = v[j] * inv;
        }
    }
    __syncthreads();

    float acc = 0.f;
    const float* mp = meta + (int64_t)b * L_ * DM_ + tid;
    #pragma unroll 4
    for (int l = 0; l < L_; l++) acc += sc[l] * mp[(int64_t)l * DM_];
    att[(int64_t)tb * DM_ + tid] = acc;
}

// ---------------- weight preprocessing ----------------
__global__ void transpose_wz(const float* __restrict__ Wzh, const float* __restrict__ Wzx,
                             const float* __restrict__ Wzb, float* __restrict__ WzT)
{
    int idx = blockIdx.x * 256 + threadIdx.x;
    int s  = idx / (4 * HYP_ * HYP_);
    int r  = idx % (4 * HYP_ * HYP_);
    int kk = r / (HYP_ * HYP_);
    int r2 = r % (HYP_ * HYP_);
    int z  = r2 / HYP_;
    int z2 = r2 % HYP_;
    const float* Wz = (s == 0) ? Wzh : ((s == 1) ? Wzx : Wzb);
    WzT[idx] = Wz[(kk * HYP_ + z2) * HYP_ + z];
}

__global__ void comp_bias(const float* __restrict__ bzh, const float* __restrict__ Wdh,
                          const float* __restrict__ bzx, const float* __restrict__ Wdx,
                          const float* __restrict__ bdb, float* __restrict__ bcomp)
{
    int n = blockIdx.x * 256 + threadIdx.x;
    if (n < 2048) {
        int kk = n >> 9;
        float s = 0.f;
        for (int z = 0; z < HYP_; z++) s += bzh[kk * HYP_ + z] * Wdh[n * HYP_ + z];
        bcomp[n] = s;
    } else if (n < 4096) {
        int m = n - 2048; int kk = m >> 9;
        float s = 0.f;
        for (int z = 0; z < HYP_; z++) s += bzx[kk * HYP_ + z] * Wdx[m * HYP_ + z];
        bcomp[n] = s;
    } else {
        bcomp[n] = bdb[n - 4096];
    }
}

__global__ void init_zero(float* __restrict__ h, float* __restrict__ c,
                          float* __restrict__ tail)
{
    int i = blockIdx.x * 256 + threadIdx.x;
    h[i] = 0.f; c[i] = 0.f; tail[i] = 0.f;
}

// ---------------- fused elementwise + LayerNorm + LSTM cell ----------------
__global__ void __launch_bounds__(512)
lstm_step(const float* __restrict__ D, const float* __restrict__ wh,
          const float* __restrict__ wx, const float* __restrict__ lng,
          const float* __restrict__ lnb, float* __restrict__ h,
          float* __restrict__ c, float* __restrict__ out,
          float* __restrict__ hT, float* __restrict__ cT)
{
    const int b  = blockIdx.x;
    const int hh = threadIdx.x;
    const int lane = hh & 31, wrp = hh >> 5;
    __shared__ float red[4][16];
    __shared__ float mu_s[4], iv_s[4];

    float y[4];
    #pragma unroll
    for (int k = 0; k < 4; k++) {
        const int idx = k * H_ + hh;
        const int64_t base = (int64_t)b * 6144;
        float dh = D[base + idx];
        float dx = D[base + 2048 + idx];
        float db = D[base + 4096 + idx];
        y[k] = dh * wh[(int64_t)b * 2048 + idx] + dx * wx[(int64_t)b * 2048 + idx] + db;
    }
    #pragma unroll
    for (int k = 0; k < 4; k++) {
        float s = y[k];
        #pragma unroll
        for (int o = 16; o; o >>= 1) s += __shfl_xor_sync(0xffffffffu, s, o);
        if (lane == 0) red[k][wrp] = s;
    }
    __syncthreads();
    if (hh < 4) {
        float s = 0.f;
        #pragma unroll
        for (int w = 0; w < 16; w++) s += red[hh][w];
        mu_s[hh] = s * (1.0f / H_);
    }
    __syncthreads();
    const float mu[4] = {mu_s[0], mu_s[1], mu_s[2], mu_s[3]};
    #pragma unroll
    for (int k = 0; k < 4; k++) {
        float d = y[k] - mu[k];
        float s = d * d;
        #pragma unroll
        for (int o = 16; o; o >>= 1) s += __shfl_xor_sync(0xffffffffu, s, o);
        if (lane == 0) red[k][wrp] = s;
    }
    __syncthreads();
    if (hh < 4) {
        float s = 0.f;
        #pragma unroll
        for (int w = 0; w < 16; w++) s += red[hh][w];
        iv_s[hh] = rsqrtf(s * (1.0f / H_) + 1e-5f);
    }
    __syncthreads();

    float yn[4];
    #pragma unroll
    for (int k = 0; k < 4; k++)
        yn[k] = (y[k] - mu[k]) * iv_s[k] * lng[k * H_ + hh] + lnb[k * H_ + hh];

    const float ig = 1.f / (1.f + expf(-yn[0]));
    const float fg = 1.f / (1.f + expf(-yn[1]));
    const float gg = tanhf(yn[2]);
    const float og = 1.f / (1.f + expf(-yn[3]));

    const int64_t bi = (int64_t)b * H_ + hh;
    const float cn = fg * c[bi] + ig * gg;
    const float hn = og * tanhf(cn);
    c[bi] = cn;  h[bi] = hn;  out[bi] = hn;
    if (hT) { hT[bi] = hn; cT[bi] = cn; }
}

// ---------------- host driver ----------------
extern "C" void kernel_launch(void* const* d_in, const int* in_sizes, int n_in,
                              void* d_out, int out_size)
{
    const float* x    = (const float*)d_in[0];
    const float* meta = (const float*)d_in[1];
    const int*   inp  = (const int*)  d_in[2];
    const float* Wq   = (const float*)d_in[3];
    const float* bq   = (const float*)d_in[4];
    const float* Wk   = (const float*)d_in[5];
    const float* bk   = (const float*)d_in[6];
    const float* Wm   = (const float*)d_in[7];
    const float* bm   = (const float*)d_in[8];
    const float* Wzh  = (const float*)d_in[9];
    const float* bzh  = (const float*)d_in[10];
    const float* Wzx  = (const float*)d_in[11];
    const float* bzx  = (const float*)d_in[12];
    const float* Wzb  = (const float*)d_in[13];
    const float* Wdh  = (const float*)d_in[14];
    const float* Wdx  = (const float*)d_in[15];
    const float* Wdb  = (const float*)d_in[16];
    const float* bdb  = (const float*)d_in[17];
    const float* w_h  = (const float*)d_in[18];
    const float* w_x  = (const float*)d_in[19];
    const float* lng  = (const float*)d_in[20];
    const float* lnb  = (const float*)d_in[21];
    float* out = (float*)d_out;

    float *pq, *pk, *patt, *pmpre, *pwx, *pWzT, *pWcomp, *pbcomp,
          *pmerged, *pD, *pwh, *ph, *pc;
    cudaGetSymbolAddress((void**)&pq,     g_q);
    cudaGetSymbolAddress((void**)&pk,     g_k);
    cudaGetSymbolAddress((void**)&patt,   g_att);
    cudaGetSymbolAddress((void**)&pmpre,  g_mpre);
    cudaGetSymbolAddress((void**)&pwx,    g_wx);
    cudaGetSymbolAddress((void**)&pWzT,   g_WzT);
    cudaGetSymbolAddress((void**)&pWcomp, g_Wcomp);
    cudaGetSymbolAddress((void**)&pbcomp, g_bcomp);
    cudaGetSymbolAddress((void**)&pmerged,g_merged);
    cudaGetSymbolAddress((void**)&pD,     g_D);
    cudaGetSymbolAddress((void**)&pwh,    g_wh);
    cudaGetSymbolAddress((void**)&ph,     g_h);
    cudaGetSymbolAddress((void**)&pc,     g_c);

    init_zero<<<1024, 256>>>(ph, pc, out + OFF_HHAT);

    // ---- weight preprocessing (fp32 exact) ----
    transpose_wz<<<3072, 256>>>(Wzh, Wzx, Wzb, pWzT);
    {
        dim3 gW(HYP_ / 128, H_ / 128, 4);
        const float* Wd[3] = {Wdh, Wdx, Wdb};
        for (int s = 0; s < 3; s++)
            sgemm128<<<gW, 256>>>(Wd[s], HYP_, (int64_t)H_ * HYP_,
                                  pWzT + (int64_t)s * 4 * HYP_ * HYP_, HYP_, (int64_t)HYP_ * HYP_,
                                  pWcomp + (int64_t)s * 4 * H_ * HYP_, HYP_, (int64_t)H_ * HYP_,
                                  nullptr, HYP_);
    }
    comp_bias<<<24, 256>>>(bzh, Wdh, bzx, Wdx, bdb, pbcomp);

    // ---- parallel (state-independent) phase — tf32 tensor GEMMs ----
    // q = x @ Wq^T + bq
    tgemm<<<dim3(HYP_/128, (T_*B_)/128), 256>>>(
        x, DIN_, Wq, DIN_, pq, HYP_, bq, nullptr, 0, DIN_, 0);
    // k = meta @ Wk^T + bk
    tgemm<<<dim3(HYP_/128, (B_*L_)/128), 256>>>(
        meta, DM_, Wk, DM_, pk, HYP_, bk, nullptr, 0, DM_, 0);
    // attention
    attn_kernel<<<T_ * B_, 256>>>(pq, pk, meta, inp, patt);
    // mergedpre = x @ Wm[:, :512]^T + bm
    tgemm<<<dim3(HYP_/128, (T_*B_)/128), 256>>>(
        x, DIN_, Wm, DIN_ + DM_ + H_, pmpre, HYP_, bm, nullptr, 0, DIN_, 0);
    // mergedpre += attended @ Wm[:, 512:768]^T
    tgemm<<<dim3(HYP_/128, (T_*B_)/128), 256>>>(
        patt, DM_, Wm + DIN_, DIN_ + DM_ + H_, pmpre, HYP_, nullptr, pmpre, HYP_, DM_, 0);
    // wx_all = x @ w_x^T  (T*B, 2048)
    tgemm<<<dim3((4*H_)/128, (T_*B_)/128), 256>>>(
        x, DIN_, w_x, DIN_, pwx, 4*H_, nullptr, nullptr, 0, DIN_, 0);

    // ---- sequential scan: 3 launches per step ----
    for (int t = 0; t < T_; t++) {
        // merged = relu(mergedpre[t] + h @ Wm[:, 768:]^T)   (scalar, 64 blocks)
        sgemm_merged<<<dim3(4, 16), 128>>>(ph, Wm + DIN_ + DM_,
                                           pmpre + (int64_t)t * B_ * HYP_, pmerged);
        // wh = h @ w_h^T | D = merged @ Wcomp^T + bcomp   (tf32 tensor)
        tgemm_dwh<<<dim3(64, B_/128), 256>>>(ph, w_h, pmerged, pWcomp, pbcomp, pwh, pD);
        // elementwise + LN + LSTM cell
        const bool last = (t == T_ - 1);
        lstm_step<<<B_, H_>>>(pD, pwh, pwx + (int64_t)t * B_ * 4 * H_, lng, lnb,
                              ph, pc, out + (int64_t)t * B_ * H_,
                              last ? out + OFF_HT : nullptr,
                              last ? out + OFF_CT : nullptr);
    }
}

// round 8
// speedup vs baseline: 1.6547x; 1.0058x over previous
#include <cuda_runtime.h>
#include <stdint.h>
#include <math.h>

// ---------------- problem constants ----------------
#define T_   128
#define B_   512
#define DIN_ 512
#define H_   512
#define DM_  256
#define HYP_ 256
#define L_   100

// output offsets (floats)
#define OUT_N      ((int64_t)T_*B_*H_)
#define OFF_HT     (OUT_N)
#define OFF_CT     (OFF_HT + (int64_t)B_*H_)
#define OFF_HHAT   (OFF_CT + (int64_t)B_*H_)

// ---------------- scratch (device globals) ----------------
__device__ float g_q   [(size_t)T_*B_*HYP_];
__device__ float g_k   [(size_t)B_*L_*HYP_];
__device__ float g_att [(size_t)T_*B_*DM_];
__device__ float g_mpre[(size_t)T_*B_*HYP_];
__device__ float g_wx  [(size_t)T_*B_*4*H_];
__device__ float g_WzT [3*4*HYP_*HYP_];
__device__ float g_Wcomp[3*4*H_*HYP_];
__device__ float g_bcomp[3*4*H_];
__device__ float g_merged[B_*HYP_];
__device__ float g_D  [(size_t)B_*3*4*H_];
__device__ float g_wh [(size_t)B_*4*H_];
__device__ float g_h  [B_*H_];
__device__ float g_c  [B_*H_];

// ================================================================
//  tf32 tensor-core GEMM:  C[m,n] = sum_k A[m,k] * W[n,k]
//  CTA tile 128x128, k-chunk 16, double buffered, 2 CTAs/SM.
//  8 warps as (wm 0..1) x (wn 0..3); warp tile 64(m) x 32(n).
//  Fragments stored PRE-PERMUTED in smem: frag loads are LDS.128 / LDS.64.
// ================================================================
__device__ __forceinline__ uint32_t f2tf32(float f) {
    uint32_t u; asm("cvt.rna.tf32.f32 %0, %1;" : "=r"(u) : "f"(f)); return u;
}

__device__ __forceinline__ void mma_tf32(float* c, const uint32_t* a, const uint32_t* b) {
    asm volatile(
        "mma.sync.aligned.m16n8k8.row.col.f32.tf32.tf32.f32 "
        "{%0,%1,%2,%3}, {%4,%5,%6,%7}, {%8,%9}, {%0,%1,%2,%3};"
        : "+f"(c[0]), "+f"(c[1]), "+f"(c[2]), "+f"(c[3])
        : "r"(a[0]), "r"(a[1]), "r"(a[2]), "r"(a[3]), "r"(b[0]), "r"(b[1]));
}

// Stage a 128x16 A tile (rows m, cols k) into permuted fragment layout.
__device__ __forceinline__ void stageA(uint32_t* As, int tid, float4 v0, float4 v1) {
    const int r = tid >> 1, chalf = (tid & 1) << 3;
    const int i = r >> 4, rr = r & 15;
    float v[8] = {v0.x, v0.y, v0.z, v0.w, v1.x, v1.y, v1.z, v1.w};
    #pragma unroll
    for (int cc = 0; cc < 8; cc++) {
        const int c = chalf + cc;
        const int s = c >> 3, k = c & 7;
        const int t   = ((rr & 7) << 2) + (k & 3);
        const int reg = (rr >> 3) + ((k >> 2) << 1);
        As[(((s << 3) + i) << 7) + (t << 2) + reg] = f2tf32(v[cc]);
    }
}

// Stage a 128x16 W tile (rows n, cols k) into B fragment layout.
__device__ __forceinline__ void stageB(uint32_t* Bs, int tid, float4 v0, float4 v1) {
    const int r = tid >> 1, chalf = (tid & 1) << 3;
    const int j = r >> 3, rr = r & 7;
    float v[8] = {v0.x, v0.y, v0.z, v0.w, v1.x, v1.y, v1.z, v1.w};
    #pragma unroll
    for (int cc = 0; cc < 8; cc++) {
        const int c = chalf + cc;
        const int s = c >> 3, k = c & 7;
        const int t   = (rr << 2) + (k & 3);
        const int reg = k >> 2;
        Bs[(((s << 4) + j) << 6) + (t << 1) + reg] = f2tf32(v[cc]);
    }
}

__device__ __forceinline__ void tgemm_core(
    const float* __restrict__ A, int lda,
    const float* __restrict__ W, int ldw,
    float* __restrict__ C, int ldc,
    const float* __restrict__ bias,
    const float* __restrict__ addsrc, int ldadd,
    int K, int relu, int64_t m0, int n0,
    uint32_t* As, uint32_t* Bs)
{
    const int tid  = threadIdx.x;
    const int lane = tid & 31, warp = tid >> 5;
    const int wm = warp >> 2, wn = warp & 3;        // wm 0..1, wn 0..3

    const float* Ap = A + (m0 + (tid >> 1)) * (int64_t)lda + ((tid & 1) << 3);
    const float* Wp = W + (int64_t)(n0 + (tid >> 1)) * ldw + ((tid & 1) << 3);

    float acc[4][4][4];
    #pragma unroll
    for (int i = 0; i < 4; i++)
        #pragma unroll
        for (int j = 0; j < 4; j++)
            #pragma unroll
            for (int p = 0; p < 4; p++) acc[i][j][p] = 0.f;

    float4 pa0 = *(const float4*)(Ap);
    float4 pa1 = *(const float4*)(Ap + 4);
    float4 pb0 = *(const float4*)(Wp);
    float4 pb1 = *(const float4*)(Wp + 4);
    stageA(As, tid, pa0, pa1);
    stageB(Bs, tid, pb0, pb1);
    __syncthreads();

    int buf = 0;
    for (int k0 = 0; k0 < K; k0 += 16) {
        const bool more = (k0 + 16) < K;
        if (more) {
            pa0 = *(const float4*)(Ap + k0 + 16);
            pa1 = *(const float4*)(Ap + k0 + 20);
            pb0 = *(const float4*)(Wp + k0 + 16);
            pb1 = *(const float4*)(Wp + k0 + 20);
        }
        const uint32_t* Ab = As + (buf << 11);
        const uint32_t* Bb = Bs + (buf << 11);
        #pragma unroll
        for (int s = 0; s < 2; s++) {
            uint32_t afr[4][4], bfr[4][2];
            #pragma unroll
            for (int mf = 0; mf < 4; mf++) {
                uint4 v = *(const uint4*)&Ab[(((s << 3) + (wm << 2) + mf) << 7) + (lane << 2)];
                afr[mf][0] = v.x; afr[mf][1] = v.y; afr[mf][2] = v.z; afr[mf][3] = v.w;
            }
            #pragma unroll
            for (int nf = 0; nf < 4; nf++) {
                uint2 v = *(const uint2*)&Bb[(((s << 4) + (wn << 2) + nf) << 6) + (lane << 1)];
                bfr[nf][0] = v.x; bfr[nf][1] = v.y;
            }
            #pragma unroll
            for (int mf = 0; mf < 4; mf++)
                #pragma unroll
                for (int nf = 0; nf < 4; nf++)
                    mma_tf32(acc[mf][nf], afr[mf], bfr[nf]);
        }
        if (more) {
            buf ^= 1;
            stageA(As + (buf << 11), tid, pa0, pa1);
            stageB(Bs + (buf << 11), tid, pb0, pb1);
            __syncthreads();
        }
    }

    // epilogue
    #pragma unroll
    for (int mf = 0; mf < 4; mf++) {
        const int64_t r0 = m0 + (wm << 6) + (mf << 4) + (lane >> 2);
        #pragma unroll
        for (int nf = 0; nf < 4; nf++) {
            const int col = n0 + (wn << 5) + (nf << 3) + ((lane & 3) << 1);
            float v0 = acc[mf][nf][0], v1 = acc[mf][nf][1];
            float v2 = acc[mf][nf][2], v3 = acc[mf][nf][3];
            if (bias) {
                float2 bb = *(const float2*)&bias[col];
                v0 += bb.x; v1 += bb.y; v2 += bb.x; v3 += bb.y;
            }
            if (addsrc) {
                float2 s0 = *(const float2*)&addsrc[r0 * ldadd + col];
                float2 s1 = *(const float2*)&addsrc[(r0 + 8) * ldadd + col];
                v0 += s0.x; v1 += s0.y; v2 += s1.x; v3 += s1.y;
            }
            if (relu) {
                v0 = fmaxf(v0, 0.f); v1 = fmaxf(v1, 0.f);
                v2 = fmaxf(v2, 0.f); v3 = fmaxf(v3, 0.f);
            }
            *(float2*)&C[r0 * ldc + col]       = make_float2(v0, v1);
            *(float2*)&C[(r0 + 8) * ldc + col] = make_float2(v2, v3);
        }
    }
}

__global__ void __launch_bounds__(256, 2)
tgemm(const float* __restrict__ A, int lda,
      const float* __restrict__ W, int ldw,
      float* __restrict__ C, int ldc,
      const float* __restrict__ bias,
      const float* __restrict__ addsrc, int ldadd,
      int K, int relu)
{
    __shared__ uint32_t As[2 * 2048];
    __shared__ uint32_t Bs[2 * 2048];
    tgemm_core(A, lda, W, ldw, C, ldc, bias, addsrc, ldadd, K, relu,
               (int64_t)blockIdx.y * 128, blockIdx.x * 128, As, Bs);
}

// per-step combined: bx<16 -> wh = h @ w_h^T ; else D = merged @ Wcomp^T + bcomp
__global__ void __launch_bounds__(256, 2)
tgemm_dwh(const float* __restrict__ h, const float* __restrict__ w_h,
          const float* __restrict__ merged, const float* __restrict__ Wcomp,
          const float* __restrict__ bcomp,
          float* __restrict__ wh, float* __restrict__ D)
{
    __shared__ uint32_t As[2 * 2048];
    __shared__ uint32_t Bs[2 * 2048];
    const int bx = blockIdx.x;
    const int64_t m0 = (int64_t)blockIdx.y * 128;
    if (bx < 16) {
        tgemm_core(h, H_, w_h, H_, wh, 4*H_, nullptr, nullptr, 0,
                   H_, 0, m0, bx * 128, As, Bs);
    } else {
        tgemm_core(merged, HYP_, Wcomp, HYP_, D, 3*4*H_, bcomp, nullptr, 0,
                   HYP_, 0, m0, (bx - 16) * 128, As, Bs);
    }
}

// ================================================================
//  scalar FFMA2 GEMM (tiny preproc GEMMs only)
// ================================================================
typedef unsigned long long u64;

__device__ __forceinline__ u64 dup2f(float a) {
    u64 r; asm("mov.b64 %0, {%1, %1};" : "=l"(r) : "f"(a)); return r;
}
__device__ __forceinline__ void fma2(u64 &c, u64 a, u64 b) {
    asm("fma.rn.f32x2 %0, %1, %2, %0;" : "+l"(c) : "l"(a), "l"(b));
}
__device__ __forceinline__ void unpk(u64 v, float &lo, float &hi) {
    asm("mov.b64 {%0, %1}, %2;" : "=f"(lo), "=f"(hi) : "l"(v));
}

__global__ void __launch_bounds__(256, 2)
sgemm128(const float* __restrict__ A, int lda, int64_t sA,
         const float* __restrict__ W, int ldw, int64_t sW,
         float* __restrict__ C, int ldc, int64_t sC,
         const float* __restrict__ bias, int K)
{
    __shared__ float As[2][16][128];
    __shared__ float Ws[2][16][128];
    const int bz = blockIdx.z;
    A += bz * sA;  W += bz * sW;  C += bz * sC;
    const int64_t m0 = (int64_t)blockIdx.y * 128;
    const int n0 = blockIdx.x * 128;

    const int tid = threadIdx.x;
    const int lr = tid >> 1;
    const int lk = (tid & 1) << 3;
    const float* Ap = A + (m0 + lr) * (int64_t)lda + lk;
    const float* Wp = W + (int64_t)(n0 + lr) * ldw + lk;
    const int tx = tid & 15, ty = tid >> 4;

    u64 acc[8][4];
    #pragma unroll
    for (int i = 0; i < 8; i++)
        #pragma unroll
        for (int j = 0; j < 4; j++) acc[i][j] = 0ull;

    float4 pa0 = *(const float4*)(Ap);
    float4 pa1 = *(const float4*)(Ap + 4);
    float4 pw0 = *(const float4*)(Wp);
    float4 pw1 = *(const float4*)(Wp + 4);
    As[0][lk+0][lr]=pa0.x; As[0][lk+1][lr]=pa0.y; As[0][lk+2][lr]=pa0.z; As[0][lk+3][lr]=pa0.w;
    As[0][lk+4][lr]=pa1.x; As[0][lk+5][lr]=pa1.y; As[0][lk+6][lr]=pa1.z; As[0][lk+7][lr]=pa1.w;
    Ws[0][lk+0][lr]=pw0.x; Ws[0][lk+1][lr]=pw0.y; Ws[0][lk+2][lr]=pw0.z; Ws[0][lk+3][lr]=pw0.w;
    Ws[0][lk+4][lr]=pw1.x; Ws[0][lk+5][lr]=pw1.y; Ws[0][lk+6][lr]=pw1.z; Ws[0][lk+7][lr]=pw1.w;
    __syncthreads();

    int buf = 0;
    for (int k0 = 0; k0 < K; k0 += 16) {
        const bool more = (k0 + 16) < K;
        if (more) {
            pa0 = *(const float4*)(Ap + k0 + 16);
            pa1 = *(const float4*)(Ap + k0 + 20);
            pw0 = *(const float4*)(Wp + k0 + 16);
            pw1 = *(const float4*)(Wp + k0 + 20);
        }
        #pragma unroll
        for (int kk = 0; kk < 16; kk++) {
            float4 a0 = *(const float4*)&As[buf][kk][ty << 3];
            float4 a1 = *(const float4*)&As[buf][kk][(ty << 3) + 4];
            const u64* bp = (const u64*)&Ws[buf][kk][tx << 3];
            u64 b0 = bp[0], b1 = bp[1], b2 = bp[2], b3 = bp[3];
            float am[8] = {a0.x, a0.y, a0.z, a0.w, a1.x, a1.y, a1.z, a1.w};
            #pragma unroll
            for (int i = 0; i < 8; i++) {
                u64 ad = dup2f(am[i]);
                fma2(acc[i][0], ad, b0);
                fma2(acc[i][1], ad, b1);
                fma2(acc[i][2], ad, b2);
                fma2(acc[i][3], ad, b3);
            }
        }
        if (more) {
            const int nb = buf ^ 1;
            As[nb][lk+0][lr]=pa0.x; As[nb][lk+1][lr]=pa0.y; As[nb][lk+2][lr]=pa0.z; As[nb][lk+3][lr]=pa0.w;
            As[nb][lk+4][lr]=pa1.x; As[nb][lk+5][lr]=pa1.y; As[nb][lk+6][lr]=pa1.z; As[nb][lk+7][lr]=pa1.w;
            Ws[nb][lk+0][lr]=pw0.x; Ws[nb][lk+1][lr]=pw0.y; Ws[nb][lk+2][lr]=pw0.z; Ws[nb][lk+3][lr]=pw0.w;
            Ws[nb][lk+4][lr]=pw1.x; Ws[nb][lk+5][lr]=pw1.y; Ws[nb][lk+6][lr]=pw1.z; Ws[nb][lk+7][lr]=pw1.w;
            __syncthreads();
            buf = nb;
        }
    }

    const int nc = n0 + (tx << 3);
    #pragma unroll
    for (int i = 0; i < 8; i++) {
        const int64_t row = m0 + (ty << 3) + i;
        float r[8];
        #pragma unroll
        for (int p = 0; p < 4; p++) {
            float lo, hi; unpk(acc[i][p], lo, hi);
            r[2*p] = lo; r[2*p+1] = hi;
        }
        if (bias) {
            float4 q0 = *(const float4*)&bias[nc];
            float4 q1 = *(const float4*)&bias[nc + 4];
            r[0]+=q0.x; r[1]+=q0.y; r[2]+=q0.z; r[3]+=q0.w;
            r[4]+=q1.x; r[5]+=q1.y; r[6]+=q1.z; r[7]+=q1.w;
        }
        *(float4*)&C[row * (int64_t)ldc + nc]     = make_float4(r[0], r[1], r[2], r[3]);
        *(float4*)&C[row * (int64_t)ldc + nc + 4] = make_float4(r[4], r[5], r[6], r[7]);
    }
}

// ---------------- small scalar GEMM: merged = relu(mpre + h @ Wm3^T) ----------------
__global__ void __launch_bounds__(128)
sgemm_merged(const float* __restrict__ h, const float* __restrict__ Wm3,
             const float* __restrict__ mpre, float* __restrict__ mg)
{
    __shared__ float As[2][16][32];
    __shared__ float Ws[2][16][64];
    const int n0 = blockIdx.x << 6;
    const int m0 = blockIdx.y << 5;
    const int tid = threadIdx.x;
    const int ar = tid >> 2, ak = (tid & 3) << 2;
    const int wr = tid >> 1, wk = (tid & 1) << 3;
    const float* Ap = h + (m0 + ar) * H_ + ak;
    const float* Wp = Wm3 + (int64_t)(n0 + wr) * (DIN_ + DM_ + H_) + wk;
    const int tx = tid & 15, ty = tid >> 4;

    float acc[4][4] = {};
    float4 a  = *(const float4*)(Ap);
    float4 w0 = *(const float4*)(Wp);
    float4 w1 = *(const float4*)(Wp + 4);
    As[0][ak+0][ar]=a.x; As[0][ak+1][ar]=a.y; As[0][ak+2][ar]=a.z; As[0][ak+3][ar]=a.w;
    Ws[0][wk+0][wr]=w0.x; Ws[0][wk+1][wr]=w0.y; Ws[0][wk+2][wr]=w0.z; Ws[0][wk+3][wr]=w0.w;
    Ws[0][wk+4][wr]=w1.x; Ws[0][wk+5][wr]=w1.y; Ws[0][wk+6][wr]=w1.z; Ws[0][wk+7][wr]=w1.w;
    __syncthreads();

    int buf = 0;
    for (int k0 = 0; k0 < H_; k0 += 16) {
        const bool more = (k0 + 16) < H_;
        if (more) {
            a  = *(const float4*)(Ap + k0 + 16);
            w0 = *(const float4*)(Wp + k0 + 16);
            w1 = *(const float4*)(Wp + k0 + 20);
        }
        #pragma unroll
        for (int kk = 0; kk < 16; kk++) {
            float4 av = *(const float4*)&As[buf][kk][ty << 2];
            float4 wv = *(const float4*)&Ws[buf][kk][tx << 2];
            float am[4] = {av.x, av.y, av.z, av.w};
            float wn[4] = {wv.x, wv.y, wv.z, wv.w};
            #pragma unroll
            for (int i = 0; i < 4; i++)
                #pragma unroll
                for (int j = 0; j < 4; j++)
                    acc[i][j] += am[i] * wn[j];
        }
        if (more) {
            const int nb = buf ^ 1;
            As[nb][ak+0][ar]=a.x; As[nb][ak+1][ar]=a.y; As[nb][ak+2][ar]=a.z; As[nb][ak+3][ar]=a.w;
            Ws[nb][wk+0][wr]=w0.x; Ws[nb][wk+1][wr]=w0.y; Ws[nb][wk+2][wr]=w0.z; Ws[nb][wk+3][wr]=w0.w;
            Ws[nb][wk+4][wr]=w1.x; Ws[nb][wk+5][wr]=w1.y; Ws[nb][wk+6][wr]=w1.z; Ws[nb][wk+7][wr]=w1.w;
            __syncthreads();
            buf = nb;
        }
    }
    const int nc = n0 + (tx << 2);
    #pragma unroll
    for (int i = 0; i < 4; i++) {
        const int row = m0 + (ty << 2) + i;
        float4 s = *(const float4*)&mpre[row * HYP_ + nc];
        float4 r;
        r.x = fmaxf(acc[i][0] + s.x, 0.f);
        r.y = fmaxf(acc[i][1] + s.y, 0.f);
        r.z = fmaxf(acc[i][2] + s.z, 0.f);
        r.w = fmaxf(acc[i][3] + s.w, 0.f);
        *(float4*)&mg[row * HYP_ + nc] = r;
    }
}

// ---------------- fused attention ----------------
__global__ void __launch_bounds__(256)
attn_kernel(const float* __restrict__ q, const float* __restrict__ k,
            const float* __restrict__ meta, const int* __restrict__ inp,
            float* __restrict__ att)
{
    const int tb = blockIdx.x;
    const int b  = tb & (B_ - 1);
    const int tid = threadIdx.x;
    __shared__ float qs[HYP_];
    __shared__ float sc[128];

    qs[tid] = q[(int64_t)tb * HYP_ + tid] * 0.0625f;
    __syncthreads();

    const int lane = tid & 31, wrp = tid >> 5;
    for (int l = wrp; l < L_; l += 8) {
        const float* kp = k + ((int64_t)b * L_ + l) * HYP_;
        float s = 0.f;
        #pragma unroll
        for (int e = 0; e < HYP_ / 32; e++)
            s += qs[lane + 32 * e] * kp[lane + 32 * e];
        #pragma unroll
        for (int o = 16; o; o >>= 1) s += __shfl_xor_sync(0xffffffffu, s, o);
        if (lane == 0) sc[l] = (inp[b * L_ + l] == 0) ? -1e9f : s;
    }
    __syncthreads();

    if (tid < 32) {
        float v[4]; float m = -3.0e38f;
        #pragma unroll
        for (int j = 0; j < 4; j++) {
            int l = tid + 32 * j;
            v[j] = (l < L_) ? sc[l] : -3.0e38f;
            m = fmaxf(m, v[j]);
        }
        #pragma unroll
        for (int o = 16; o; o >>= 1) m = fmaxf(m, __shfl_xor_sync(0xffffffffu, m, o));
        float s = 0.f;
        #pragma unroll
        for (int j = 0; j < 4; j++) { v[j] = expf(v[j] - m); s += v[j]; }
        #pragma unroll
        for (int o = 16; o; o >>= 1) s += __shfl_xor_sync(0xffffffffu, s, o);
        const float inv = 1.0f / s;
        #pragma unroll
        for (int j = 0; j < 4; j++) {
            int l = tid + 32 * j;
            if (l < L_) sc[l] = v[j] * inv;
        }
    }
    __syncthreads();

    float acc = 0.f;
    const float* mp = meta + (int64_t)b * L_ * DM_ + tid;
    #pragma unroll 4
    for (int l = 0; l < L_; l++) acc += sc[l] * mp[(int64_t)l * DM_];
    att[(int64_t)tb * DM_ + tid] = acc;
}

// ---------------- weight preprocessing ----------------
__global__ void transpose_wz(const float* __restrict__ Wzh, const float* __restrict__ Wzx,
                             const float* __restrict__ Wzb, float* __restrict__ WzT)
{
    int idx = blockIdx.x * 256 + threadIdx.x;
    int s  = idx / (4 * HYP_ * HYP_);
    int r  = idx % (4 * HYP_ * HYP_);
    int kk = r / (HYP_ * HYP_);
    int r2 = r % (HYP_ * HYP_);
    int z  = r2 / HYP_;
    int z2 = r2 % HYP_;
    const float* Wz = (s == 0) ? Wzh : ((s == 1) ? Wzx : Wzb);
    WzT[idx] = Wz[(kk * HYP_ + z2) * HYP_ + z];
}

__global__ void comp_bias(const float* __restrict__ bzh, const float* __restrict__ Wdh,
                          const float* __restrict__ bzx, const float* __restrict__ Wdx,
                          const float* __restrict__ bdb, float* __restrict__ bcomp)
{
    int n = blockIdx.x * 256 + threadIdx.x;
    if (n < 2048) {
        int kk = n >> 9;
        float s = 0.f;
        for (int z = 0; z < HYP_; z++) s += bzh[kk * HYP_ + z] * Wdh[n * HYP_ + z];
        bcomp[n] = s;
    } else if (n < 4096) {
        int m = n - 2048; int kk = m >> 9;
        float s = 0.f;
        for (int z = 0; z < HYP_; z++) s += bzx[kk * HYP_ + z] * Wdx[m * HYP_ + z];
        bcomp[n] = s;
    } else {
        bcomp[n] = bdb[n - 4096];
    }
}

__global__ void init_zero(float* __restrict__ h, float* __restrict__ c,
                          float* __restrict__ tail)
{
    int i = blockIdx.x * 256 + threadIdx.x;
    h[i] = 0.f; c[i] = 0.f; tail[i] = 0.f;
}

// ---------------- fused elementwise + LayerNorm + LSTM cell ----------------
__global__ void __launch_bounds__(512)
lstm_step(const float* __restrict__ D, const float* __restrict__ wh,
          const float* __restrict__ wx, const float* __restrict__ lng,
          const float* __restrict__ lnb, float* __restrict__ h,
          float* __restrict__ c, float* __restrict__ out,
          float* __restrict__ hT, float* __restrict__ cT)
{
    const int b  = blockIdx.x;
    const int hh = threadIdx.x;
    const int lane = hh & 31, wrp = hh >> 5;
    __shared__ float red[4][16];
    __shared__ float mu_s[4], iv_s[4];

    float y[4];
    #pragma unroll
    for (int k = 0; k < 4; k++) {
        const int idx = k * H_ + hh;
        const int64_t base = (int64_t)b * 6144;
        float dh = D[base + idx];
        float dx = D[base + 2048 + idx];
        float db = D[base + 4096 + idx];
        y[k] = dh * wh[(int64_t)b * 2048 + idx] + dx * wx[(int64_t)b * 2048 + idx] + db;
    }
    #pragma unroll
    for (int k = 0; k < 4; k++) {
        float s = y[k];
        #pragma unroll
        for (int o = 16; o; o >>= 1) s += __shfl_xor_sync(0xffffffffu, s, o);
        if (lane == 0) red[k][wrp] = s;
    }
    __syncthreads();
    if (hh < 4) {
        float s = 0.f;
        #pragma unroll
        for (int w = 0; w < 16; w++) s += red[hh][w];
        mu_s[hh] = s * (1.0f / H_);
    }
    __syncthreads();
    const float mu[4] = {mu_s[0], mu_s[1], mu_s[2], mu_s[3]};
    #pragma unroll
    for (int k = 0; k < 4; k++) {
        float d = y[k] - mu[k];
        float s = d * d;
        #pragma unroll
        for (int o = 16; o; o >>= 1) s += __shfl_xor_sync(0xffffffffu, s, o);
        if (lane == 0) red[k][wrp] = s;
    }
    __syncthreads();
    if (hh < 4) {
        float s = 0.f;
        #pragma unroll
        for (int w = 0; w < 16; w++) s += red[hh][w];
        iv_s[hh] = rsqrtf(s * (1.0f / H_) + 1e-5f);
    }
    __syncthreads();

    float yn[4];
    #pragma unroll
    for (int k = 0; k < 4; k++)
        yn[k] = (y[k] - mu[k]) * iv_s[k] * lng[k * H_ + hh] + lnb[k * H_ + hh];

    const float ig = 1.f / (1.f + expf(-yn[0]));
    const float fg = 1.f / (1.f + expf(-yn[1]));
    const float gg = tanhf(yn[2]);
    const float og = 1.f / (1.f + expf(-yn[3]));

    const int64_t bi = (int64_t)b * H_ + hh;
    const float cn = fg * c[bi] + ig * gg;
    const float hn = og * tanhf(cn);
    c[bi] = cn;  h[bi] = hn;  out[bi] = hn;
    if (hT) { hT[bi] = hn; cT[bi] = cn; }
}

// ---------------- host driver ----------------
extern "C" void kernel_launch(void* const* d_in, const int* in_sizes, int n_in,
                              void* d_out, int out_size)
{
    const float* x    = (const float*)d_in[0];
    const float* meta = (const float*)d_in[1];
    const int*   inp  = (const int*)  d_in[2];
    const float* Wq   = (const float*)d_in[3];
    const float* bq   = (const float*)d_in[4];
    const float* Wk   = (const float*)d_in[5];
    const float* bk   = (const float*)d_in[6];
    const float* Wm   = (const float*)d_in[7];
    const float* bm   = (const float*)d_in[8];
    const float* Wzh  = (const float*)d_in[9];
    const float* bzh  = (const float*)d_in[10];
    const float* Wzx  = (const float*)d_in[11];
    const float* bzx  = (const float*)d_in[12];
    const float* Wzb  = (const float*)d_in[13];
    const float* Wdh  = (const float*)d_in[14];
    const float* Wdx  = (const float*)d_in[15];
    const float* Wdb  = (const float*)d_in[16];
    const float* bdb  = (const float*)d_in[17];
    const float* w_h  = (const float*)d_in[18];
    const float* w_x  = (const float*)d_in[19];
    const float* lng  = (const float*)d_in[20];
    const float* lnb  = (const float*)d_in[21];
    float* out = (float*)d_out;

    float *pq, *pk, *patt, *pmpre, *pwx, *pWzT, *pWcomp, *pbcomp,
          *pmerged, *pD, *pwh, *ph, *pc;
    cudaGetSymbolAddress((void**)&pq,     g_q);
    cudaGetSymbolAddress((void**)&pk,     g_k);
    cudaGetSymbolAddress((void**)&patt,   g_att);
    cudaGetSymbolAddress((void**)&pmpre,  g_mpre);
    cudaGetSymbolAddress((void**)&pwx,    g_wx);
    cudaGetSymbolAddress((void**)&pWzT,   g_WzT);
    cudaGetSymbolAddress((void**)&pWcomp, g_Wcomp);
    cudaGetSymbolAddress((void**)&pbcomp, g_bcomp);
    cudaGetSymbolAddress((void**)&pmerged,g_merged);
    cudaGetSymbolAddress((void**)&pD,     g_D);
    cudaGetSymbolAddress((void**)&pwh,    g_wh);
    cudaGetSymbolAddress((void**)&ph,     g_h);
    cudaGetSymbolAddress((void**)&pc,     g_c);

    // launch order arranged so ncu (-s 5 -c 1) samples the big wx tgemm (#5)
    init_zero<<<1024, 256>>>(ph, pc, out + OFF_HHAT);                       // 0
    tgemm<<<dim3(HYP_/128, (T_*B_)/128), 256>>>(                            // 1: q
        x, DIN_, Wq, DIN_, pq, HYP_, bq, nullptr, 0, DIN_, 0);
    tgemm<<<dim3(HYP_/128, (B_*L_)/128), 256>>>(                            // 2: k
        meta, DM_, Wk, DM_, pk, HYP_, bk, nullptr, 0, DM_, 0);
    tgemm<<<dim3(HYP_/128, (T_*B_)/128), 256>>>(                            // 3: mpre
        x, DIN_, Wm, DIN_ + DM_ + H_, pmpre, HYP_, bm, nullptr, 0, DIN_, 0);
    attn_kernel<<<T_ * B_, 256>>>(pq, pk, meta, inp, patt);                 // 4
    tgemm<<<dim3((4*H_)/128, (T_*B_)/128), 256>>>(                          // 5: wx (BIG)
        x, DIN_, w_x, DIN_, pwx, 4*H_, nullptr, nullptr, 0, DIN_, 0);
    tgemm<<<dim3(HYP_/128, (T_*B_)/128), 256>>>(                            // 6: mpre += att@Wm2
        patt, DM_, Wm + DIN_, DIN_ + DM_ + H_, pmpre, HYP_, nullptr, pmpre, HYP_, DM_, 0);

    // ---- weight preprocessing (fp32 exact) ----
    transpose_wz<<<3072, 256>>>(Wzh, Wzx, Wzb, pWzT);
    {
        dim3 gW(HYP_ / 128, H_ / 128, 4);
        const float* Wd[3] = {Wdh, Wdx, Wdb};
        for (int s = 0; s < 3; s++)
            sgemm128<<<gW, 256>>>(Wd[s], HYP_, (int64_t)H_ * HYP_,
                                  pWzT + (int64_t)s * 4 * HYP_ * HYP_, HYP_, (int64_t)HYP_ * HYP_,
                                  pWcomp + (int64_t)s * 4 * H_ * HYP_, HYP_, (int64_t)H_ * HYP_,
                                  nullptr, HYP_);
    }
    comp_bias<<<24, 256>>>(bzh, Wdh, bzx, Wdx, bdb, pbcomp);

    // ---- sequential scan: 3 launches per step ----
    for (int t = 0; t < T_; t++) {
        sgemm_merged<<<dim3(4, 16), 128>>>(ph, Wm + DIN_ + DM_,
                                           pmpre + (int64_t)t * B_ * HYP_, pmerged);
        tgemm_dwh<<<dim3(64, B_/128), 256>>>(ph, w_h, pmerged, pWcomp, pbcomp, pwh, pD);
        const bool last = (t == T_ - 1);
        lstm_step<<<B_, H_>>>(pD, pwh, pwx + (int64_t)t * B_ * 4 * H_, lng, lnb,
                              ph, pc, out + (int64_t)t * B_ * H_,
                              last ? out + OFF_HT : nullptr,
                              last ? out + OFF_CT : nullptr);
    }
}

// round 9
// speedup vs baseline: 2.0920x; 1.2643x over previous
#include <cuda_runtime.h>
#include <stdint.h>
#include <math.h>

// ---------------- problem constants ----------------
#define T_   128
#define B_   512
#define DIN_ 512
#define H_   512
#define DM_  256
#define HYP_ 256
#define L_   100

// output offsets (floats)
#define OUT_N      ((int64_t)T_*B_*H_)
#define OFF_HT     (OUT_N)
#define OFF_CT     (OFF_HT + (int64_t)B_*H_)
#define OFF_HHAT   (OFF_CT + (int64_t)B_*H_)

// ---------------- scratch (device globals) ----------------
__device__ float g_q   [(size_t)T_*B_*HYP_];
__device__ float g_k   [(size_t)B_*L_*HYP_];
__device__ float g_att [(size_t)T_*B_*DM_];
__device__ float g_mpre[(size_t)T_*B_*HYP_];
__device__ float g_wx  [(size_t)T_*B_*4*H_];
__device__ float g_WzT [3*4*HYP_*HYP_];
__device__ float g_Wcomp[3*4*H_*HYP_];
__device__ float g_bcomp[3*4*H_];
__device__ float g_merged[B_*HYP_];
__device__ float g_D  [(size_t)B_*3*4*H_];
__device__ float g_wh [(size_t)B_*4*H_];
__device__ float g_h  [B_*H_];
__device__ float g_c  [B_*H_];

// ================================================================
//  tf32 tensor-core GEMM:  C[m,n] = sum_k A[m,k] * W[n,k]
//  CTA tile 128x128, k-chunk 16, double buffered, 2 CTAs/SM.
//  Fragment layout in smem is bank-SWIZZLED: staging stores go from
//  8-way to 2-way conflicts; fragment loads remain LDS.128/LDS.64
//  conflict-free (swizzle is a bijection on the lane index).
// ================================================================
__device__ __forceinline__ uint32_t f2tf32(float f) {
    uint32_t u; asm("cvt.rna.tf32.f32 %0, %1;" : "=r"(u) : "f"(f)); return u;
}

__device__ __forceinline__ void mma_tf32(float* c, const uint32_t* a, const uint32_t* b) {
    asm volatile(
        "mma.sync.aligned.m16n8k8.row.col.f32.tf32.tf32.f32 "
        "{%0,%1,%2,%3}, {%4,%5,%6,%7}, {%8,%9}, {%0,%1,%2,%3};"
        : "+f"(c[0]), "+f"(c[1]), "+f"(c[2]), "+f"(c[3])
        : "r"(a[0]), "r"(a[1]), "r"(a[2]), "r"(a[3]), "r"(b[0]), "r"(b[1]));
}

// Stage a 128x16 A tile (rows m, cols k) into swizzled fragment layout.
// Fragment element (rr,k): t = (rr&7)*4 + (k&3); stored at tsw = t ^ ((t>>3)&3).
__device__ __forceinline__ void stageA(uint32_t* As, int tid, float4 v0, float4 v1) {
    const int r = tid >> 1, chalf = (tid & 1) << 3;
    const int i = r >> 4, rr = r & 15;
    float v[8] = {v0.x, v0.y, v0.z, v0.w, v1.x, v1.y, v1.z, v1.w};
    #pragma unroll
    for (int cc = 0; cc < 8; cc++) {
        const int c = chalf + cc;
        const int s = c >> 3, k = c & 7;
        const int t   = ((rr & 7) << 2) + (k & 3);
        const int tsw = t ^ ((t >> 3) & 3);
        const int reg = (rr >> 3) + ((k >> 2) << 1);
        As[(((s << 3) + i) << 7) + (tsw << 2) + reg] = f2tf32(v[cc]);
    }
}

// Stage a 128x16 W tile (rows n, cols k) into swizzled B fragment layout.
// t = rr*4 + (k&3); stored at tsw = t ^ ((t>>3)&3) ^ (j&1).
__device__ __forceinline__ void stageB(uint32_t* Bs, int tid, float4 v0, float4 v1) {
    const int r = tid >> 1, chalf = (tid & 1) << 3;
    const int j = r >> 3, rr = r & 7;
    float v[8] = {v0.x, v0.y, v0.z, v0.w, v1.x, v1.y, v1.z, v1.w};
    #pragma unroll
    for (int cc = 0; cc < 8; cc++) {
        const int c = chalf + cc;
        const int s = c >> 3, k = c & 7;
        const int t   = (rr << 2) + (k & 3);
        const int tsw = (t ^ ((t >> 3) & 3)) ^ (j & 1);
        const int reg = k >> 2;
        Bs[(((s << 4) + j) << 6) + (tsw << 1) + reg] = f2tf32(v[cc]);
    }
}

__device__ __forceinline__ void tgemm_core(
    const float* __restrict__ A, int lda,
    const float* __restrict__ W, int ldw,
    float* __restrict__ C, int ldc,
    const float* __restrict__ bias,
    const float* __restrict__ addsrc, int ldadd,
    int K, int relu, int64_t m0, int n0,
    uint32_t* As, uint32_t* Bs)
{
    const int tid  = threadIdx.x;
    const int lane = tid & 31, warp = tid >> 5;
    const int wm = warp >> 2, wn = warp & 3;        // wm 0..1, wn 0..3
    const int lswA  = lane ^ ((lane >> 3) & 3);     // A-frag load swizzle
    const int lswB0 = lswA;                         // B-frag, even j
    const int lswB1 = lswA ^ 1;                     // B-frag, odd j

    const float* Ap = A + (m0 + (tid >> 1)) * (int64_t)lda + ((tid & 1) << 3);
    const float* Wp = W + (int64_t)(n0 + (tid >> 1)) * ldw + ((tid & 1) << 3);

    float acc[4][4][4];
    #pragma unroll
    for (int i = 0; i < 4; i++)
        #pragma unroll
        for (int j = 0; j < 4; j++)
            #pragma unroll
            for (int p = 0; p < 4; p++) acc[i][j][p] = 0.f;

    float4 pa0 = *(const float4*)(Ap);
    float4 pa1 = *(const float4*)(Ap + 4);
    float4 pb0 = *(const float4*)(Wp);
    float4 pb1 = *(const float4*)(Wp + 4);
    stageA(As, tid, pa0, pa1);
    stageB(Bs, tid, pb0, pb1);
    __syncthreads();

    int buf = 0;
    for (int k0 = 0; k0 < K; k0 += 16) {
        const bool more = (k0 + 16) < K;
        if (more) {
            pa0 = *(const float4*)(Ap + k0 + 16);
            pa1 = *(const float4*)(Ap + k0 + 20);
            pb0 = *(const float4*)(Wp + k0 + 16);
            pb1 = *(const float4*)(Wp + k0 + 20);
        }
        const uint32_t* Ab = As + (buf << 11);
        const uint32_t* Bb = Bs + (buf << 11);
        #pragma unroll
        for (int s = 0; s < 2; s++) {
            uint32_t afr[4][4], bfr[4][2];
            #pragma unroll
            for (int mf = 0; mf < 4; mf++) {
                uint4 v = *(const uint4*)&Ab[(((s << 3) + (wm << 2) + mf) << 7) + (lswA << 2)];
                afr[mf][0] = v.x; afr[mf][1] = v.y; afr[mf][2] = v.z; afr[mf][3] = v.w;
            }
            #pragma unroll
            for (int nf = 0; nf < 4; nf++) {
                const int jg = (wn << 2) + nf;
                const int ls = (nf & 1) ? lswB1 : lswB0;
                uint2 v = *(const uint2*)&Bb[(((s << 4) + jg) << 6) + (ls << 1)];
                bfr[nf][0] = v.x; bfr[nf][1] = v.y;
            }
            #pragma unroll
            for (int mf = 0; mf < 4; mf++)
                #pragma unroll
                for (int nf = 0; nf < 4; nf++)
                    mma_tf32(acc[mf][nf], afr[mf], bfr[nf]);
        }
        if (more) {
            buf ^= 1;
            stageA(As + (buf << 11), tid, pa0, pa1);
            stageB(Bs + (buf << 11), tid, pb0, pb1);
            __syncthreads();
        }
    }

    // epilogue
    #pragma unroll
    for (int mf = 0; mf < 4; mf++) {
        const int64_t r0 = m0 + (wm << 6) + (mf << 4) + (lane >> 2);
        #pragma unroll
        for (int nf = 0; nf < 4; nf++) {
            const int col = n0 + (wn << 5) + (nf << 3) + ((lane & 3) << 1);
            float v0 = acc[mf][nf][0], v1 = acc[mf][nf][1];
            float v2 = acc[mf][nf][2], v3 = acc[mf][nf][3];
            if (bias) {
                float2 bb = *(const float2*)&bias[col];
                v0 += bb.x; v1 += bb.y; v2 += bb.x; v3 += bb.y;
            }
            if (addsrc) {
                float2 s0 = *(const float2*)&addsrc[r0 * ldadd + col];
                float2 s1 = *(const float2*)&addsrc[(r0 + 8) * ldadd + col];
                v0 += s0.x; v1 += s0.y; v2 += s1.x; v3 += s1.y;
            }
            if (relu) {
                v0 = fmaxf(v0, 0.f); v1 = fmaxf(v1, 0.f);
                v2 = fmaxf(v2, 0.f); v3 = fmaxf(v3, 0.f);
            }
            *(float2*)&C[r0 * ldc + col]       = make_float2(v0, v1);
            *(float2*)&C[(r0 + 8) * ldc + col] = make_float2(v2, v3);
        }
    }
}

__global__ void __launch_bounds__(256, 2)
tgemm(const float* __restrict__ A, int lda,
      const float* __restrict__ W, int ldw,
      float* __restrict__ C, int ldc,
      const float* __restrict__ bias,
      const float* __restrict__ addsrc, int ldadd,
      int K, int relu)
{
    __shared__ uint32_t As[2 * 2048];
    __shared__ uint32_t Bs[2 * 2048];
    tgemm_core(A, lda, W, ldw, C, ldc, bias, addsrc, ldadd, K, relu,
               (int64_t)blockIdx.y * 128, blockIdx.x * 128, As, Bs);
}

// per-step combined: bx<16 -> wh = h @ w_h^T ; else D = merged @ Wcomp^T + bcomp
__global__ void __launch_bounds__(256, 2)
tgemm_dwh(const float* __restrict__ h, const float* __restrict__ w_h,
          const float* __restrict__ merged, const float* __restrict__ Wcomp,
          const float* __restrict__ bcomp,
          float* __restrict__ wh, float* __restrict__ D)
{
    __shared__ uint32_t As[2 * 2048];
    __shared__ uint32_t Bs[2 * 2048];
    const int bx = blockIdx.x;
    const int64_t m0 = (int64_t)blockIdx.y * 128;
    if (bx < 16) {
        tgemm_core(h, H_, w_h, H_, wh, 4*H_, nullptr, nullptr, 0,
                   H_, 0, m0, bx * 128, As, Bs);
    } else {
        tgemm_core(merged, HYP_, Wcomp, HYP_, D, 3*4*H_, bcomp, nullptr, 0,
                   HYP_, 0, m0, (bx - 16) * 128, As, Bs);
    }
}

// ================================================================
//  scalar FFMA2 GEMM (tiny preproc GEMMs only)
// ================================================================
typedef unsigned long long u64;

__device__ __forceinline__ u64 dup2f(float a) {
    u64 r; asm("mov.b64 %0, {%1, %1};" : "=l"(r) : "f"(a)); return r;
}
__device__ __forceinline__ void fma2(u64 &c, u64 a, u64 b) {
    asm("fma.rn.f32x2 %0, %1, %2, %0;" : "+l"(c) : "l"(a), "l"(b));
}
__device__ __forceinline__ void unpk(u64 v, float &lo, float &hi) {
    asm("mov.b64 {%0, %1}, %2;" : "=f"(lo), "=f"(hi) : "l"(v));
}

__global__ void __launch_bounds__(256, 2)
sgemm128(const float* __restrict__ A, int lda, int64_t sA,
         const float* __restrict__ W, int ldw, int64_t sW,
         float* __restrict__ C, int ldc, int64_t sC,
         const float* __restrict__ bias, int K)
{
    __shared__ float As[2][16][128];
    __shared__ float Ws[2][16][128];
    const int bz = blockIdx.z;
    A += bz * sA;  W += bz * sW;  C += bz * sC;
    const int64_t m0 = (int64_t)blockIdx.y * 128;
    const int n0 = blockIdx.x * 128;

    const int tid = threadIdx.x;
    const int lr = tid >> 1;
    const int lk = (tid & 1) << 3;
    const float* Ap = A + (m0 + lr) * (int64_t)lda + lk;
    const float* Wp = W + (int64_t)(n0 + lr) * ldw + lk;
    const int tx = tid & 15, ty = tid >> 4;

    u64 acc[8][4];
    #pragma unroll
    for (int i = 0; i < 8; i++)
        #pragma unroll
        for (int j = 0; j < 4; j++) acc[i][j] = 0ull;

    float4 pa0 = *(const float4*)(Ap);
    float4 pa1 = *(const float4*)(Ap + 4);
    float4 pw0 = *(const float4*)(Wp);
    float4 pw1 = *(const float4*)(Wp + 4);
    As[0][lk+0][lr]=pa0.x; As[0][lk+1][lr]=pa0.y; As[0][lk+2][lr]=pa0.z; As[0][lk+3][lr]=pa0.w;
    As[0][lk+4][lr]=pa1.x; As[0][lk+5][lr]=pa1.y; As[0][lk+6][lr]=pa1.z; As[0][lk+7][lr]=pa1.w;
    Ws[0][lk+0][lr]=pw0.x; Ws[0][lk+1][lr]=pw0.y; Ws[0][lk+2][lr]=pw0.z; Ws[0][lk+3][lr]=pw0.w;
    Ws[0][lk+4][lr]=pw1.x; Ws[0][lk+5][lr]=pw1.y; Ws[0][lk+6][lr]=pw1.z; Ws[0][lk+7][lr]=pw1.w;
    __syncthreads();

    int buf = 0;
    for (int k0 = 0; k0 < K; k0 += 16) {
        const bool more = (k0 + 16) < K;
        if (more) {
            pa0 = *(const float4*)(Ap + k0 + 16);
            pa1 = *(const float4*)(Ap + k0 + 20);
            pw0 = *(const float4*)(Wp + k0 + 16);
            pw1 = *(const float4*)(Wp + k0 + 20);
        }
        #pragma unroll
        for (int kk = 0; kk < 16; kk++) {
            float4 a0 = *(const float4*)&As[buf][kk][ty << 3];
            float4 a1 = *(const float4*)&As[buf][kk][(ty << 3) + 4];
            const u64* bp = (const u64*)&Ws[buf][kk][tx << 3];
            u64 b0 = bp[0], b1 = bp[1], b2 = bp[2], b3 = bp[3];
            float am[8] = {a0.x, a0.y, a0.z, a0.w, a1.x, a1.y, a1.z, a1.w};
            #pragma unroll
            for (int i = 0; i < 8; i++) {
                u64 ad = dup2f(am[i]);
                fma2(acc[i][0], ad, b0);
                fma2(acc[i][1], ad, b1);
                fma2(acc[i][2], ad, b2);
                fma2(acc[i][3], ad, b3);
            }
        }
        if (more) {
            const int nb = buf ^ 1;
            As[nb][lk+0][lr]=pa0.x; As[nb][lk+1][lr]=pa0.y; As[nb][lk+2][lr]=pa0.z; As[nb][lk+3][lr]=pa0.w;
            As[nb][lk+4][lr]=pa1.x; As[nb][lk+5][lr]=pa1.y; As[nb][lk+6][lr]=pa1.z; As[nb][lk+7][lr]=pa1.w;
            Ws[nb][lk+0][lr]=pw0.x; Ws[nb][lk+1][lr]=pw0.y; Ws[nb][lk+2][lr]=pw0.z; Ws[nb][lk+3][lr]=pw0.w;
            Ws[nb][lk+4][lr]=pw1.x; Ws[nb][lk+5][lr]=pw1.y; Ws[nb][lk+6][lr]=pw1.z; Ws[nb][lk+7][lr]=pw1.w;
            __syncthreads();
            buf = nb;
        }
    }

    const int nc = n0 + (tx << 3);
    #pragma unroll
    for (int i = 0; i < 8; i++) {
        const int64_t row = m0 + (ty << 3) + i;
        float r[8];
        #pragma unroll
        for (int p = 0; p < 4; p++) {
            float lo, hi; unpk(acc[i][p], lo, hi);
            r[2*p] = lo; r[2*p+1] = hi;
        }
        if (bias) {
            float4 q0 = *(const float4*)&bias[nc];
            float4 q1 = *(const float4*)&bias[nc + 4];
            r[0]+=q0.x; r[1]+=q0.y; r[2]+=q0.z; r[3]+=q0.w;
            r[4]+=q1.x; r[5]+=q1.y; r[6]+=q1.z; r[7]+=q1.w;
        }
        *(float4*)&C[row * (int64_t)ldc + nc]     = make_float4(r[0], r[1], r[2], r[3]);
        *(float4*)&C[row * (int64_t)ldc + nc + 4] = make_float4(r[4], r[5], r[6], r[7]);
    }
}

// ---------------- small scalar GEMM: merged = relu(mpre + h @ Wm3^T) ----------------
__global__ void __launch_bounds__(128)
sgemm_merged(const float* __restrict__ h, const float* __restrict__ Wm3,
             const float* __restrict__ mpre, float* __restrict__ mg)
{
    __shared__ float As[2][16][32];
    __shared__ float Ws[2][16][64];
    const int n0 = blockIdx.x << 6;
    const int m0 = blockIdx.y << 5;
    const int tid = threadIdx.x;
    const int ar = tid >> 2, ak = (tid & 3) << 2;
    const int wr = tid >> 1, wk = (tid & 1) << 3;
    const float* Ap = h + (m0 + ar) * H_ + ak;
    const float* Wp = Wm3 + (int64_t)(n0 + wr) * (DIN_ + DM_ + H_) + wk;
    const int tx = tid & 15, ty = tid >> 4;

    float acc[4][4] = {};
    float4 a  = *(const float4*)(Ap);
    float4 w0 = *(const float4*)(Wp);
    float4 w1 = *(const float4*)(Wp + 4);
    As[0][ak+0][ar]=a.x; As[0][ak+1][ar]=a.y; As[0][ak+2][ar]=a.z; As[0][ak+3][ar]=a.w;
    Ws[0][wk+0][wr]=w0.x; Ws[0][wk+1][wr]=w0.y; Ws[0][wk+2][wr]=w0.z; Ws[0][wk+3][wr]=w0.w;
    Ws[0][wk+4][wr]=w1.x; Ws[0][wk+5][wr]=w1.y; Ws[0][wk+6][wr]=w1.z; Ws[0][wk+7][wr]=w1.w;
    __syncthreads();

    int buf = 0;
    for (int k0 = 0; k0 < H_; k0 += 16) {
        const bool more = (k0 + 16) < H_;
        if (more) {
            a  = *(const float4*)(Ap + k0 + 16);
            w0 = *(const float4*)(Wp + k0 + 16);
            w1 = *(const float4*)(Wp + k0 + 20);
        }
        #pragma unroll
        for (int kk = 0; kk < 16; kk++) {
            float4 av = *(const float4*)&As[buf][kk][ty << 2];
            float4 wv = *(const float4*)&Ws[buf][kk][tx << 2];
            float am[4] = {av.x, av.y, av.z, av.w};
            float wn[4] = {wv.x, wv.y, wv.z, wv.w};
            #pragma unroll
            for (int i = 0; i < 4; i++)
                #pragma unroll
                for (int j = 0; j < 4; j++)
                    acc[i][j] += am[i] * wn[j];
        }
        if (more) {
            const int nb = buf ^ 1;
            As[nb][ak+0][ar]=a.x; As[nb][ak+1][ar]=a.y; As[nb][ak+2][ar]=a.z; As[nb][ak+3][ar]=a.w;
            Ws[nb][wk+0][wr]=w0.x; Ws[nb][wk+1][wr]=w0.y; Ws[nb][wk+2][wr]=w0.z; Ws[nb][wk+3][wr]=w0.w;
            Ws[nb][wk+4][wr]=w1.x; Ws[nb][wk+5][wr]=w1.y; Ws[nb][wk+6][wr]=w1.z; Ws[nb][wk+7][wr]=w1.w;
            __syncthreads();
            buf = nb;
        }
    }
    const int nc = n0 + (tx << 2);
    #pragma unroll
    for (int i = 0; i < 4; i++) {
        const int row = m0 + (ty << 2) + i;
        float4 s = *(const float4*)&mpre[row * HYP_ + nc];
        float4 r;
        r.x = fmaxf(acc[i][0] + s.x, 0.f);
        r.y = fmaxf(acc[i][1] + s.y, 0.f);
        r.z = fmaxf(acc[i][2] + s.z, 0.f);
        r.w = fmaxf(acc[i][3] + s.w, 0.f);
        *(float4*)&mg[row * HYP_ + nc] = r;
    }
}

// ---------------- fused attention ----------------
__global__ void __launch_bounds__(256)
attn_kernel(const float* __restrict__ q, const float* __restrict__ k,
            const float* __restrict__ meta, const int* __restrict__ inp,
            float* __restrict__ att)
{
    const int tb = blockIdx.x;
    const int b  = tb & (B_ - 1);
    const int tid = threadIdx.x;
    __shared__ float qs[HYP_];
    __shared__ float sc[128];

    qs[tid] = q[(int64_t)tb * HYP_ + tid] * 0.0625f;
    __syncthreads();

    const int lane = tid & 31, wrp = tid >> 5;
    for (int l = wrp; l < L_; l += 8) {
        const float* kp = k + ((int64_t)b * L_ + l) * HYP_;
        float s = 0.f;
        #pragma unroll
        for (int e = 0; e < HYP_ / 32; e++)
            s += qs[lane + 32 * e] * kp[lane + 32 * e];
        #pragma unroll
        for (int o = 16; o; o >>= 1) s += __shfl_xor_sync(0xffffffffu, s, o);
        if (lane == 0) sc[l] = (inp[b * L_ + l] == 0) ? -1e9f : s;
    }
    __syncthreads();

    if (tid < 32) {
        float v[4]; float m = -3.0e38f;
        #pragma unroll
        for (int j = 0; j < 4; j++) {
            int l = tid + 32 * j;
            v[j] = (l < L_) ? sc[l] : -3.0e38f;
            m = fmaxf(m, v[j]);
        }
        #pragma unroll
        for (int o = 16; o; o >>= 1) m = fmaxf(m, __shfl_xor_sync(0xffffffffu, m, o));
        float s = 0.f;
        #pragma unroll
        for (int j = 0; j < 4; j++) { v[j] = expf(v[j] - m); s += v[j]; }
        #pragma unroll
        for (int o = 16; o; o >>= 1) s += __shfl_xor_sync(0xffffffffu, s, o);
        const float inv = 1.0f / s;
        #pragma unroll
        for (int j = 0; j < 4; j++) {
            int l = tid + 32 * j;
            if (l < L_) sc[l] = v[j] * inv;
        }
    }
    __syncthreads();

    float acc = 0.f;
    const float* mp = meta + (int64_t)b * L_ * DM_ + tid;
    #pragma unroll 4
    for (int l = 0; l < L_; l++) acc += sc[l] * mp[(int64_t)l * DM_];
    att[(int64_t)tb * DM_ + tid] = acc;
}

// ---------------- weight preprocessing ----------------
__global__ void transpose_wz(const float* __restrict__ Wzh, const float* __restrict__ Wzx,
                             const float* __restrict__ Wzb, float* __restrict__ WzT)
{
    int idx = blockIdx.x * 256 + threadIdx.x;
    int s  = idx / (4 * HYP_ * HYP_);
    int r  = idx % (4 * HYP_ * HYP_);
    int kk = r / (HYP_ * HYP_);
    int r2 = r % (HYP_ * HYP_);
    int z  = r2 / HYP_;
    int z2 = r2 % HYP_;
    const float* Wz = (s == 0) ? Wzh : ((s == 1) ? Wzx : Wzb);
    WzT[idx] = Wz[(kk * HYP_ + z2) * HYP_ + z];
}

__global__ void comp_bias(const float* __restrict__ bzh, const float* __restrict__ Wdh,
                          const float* __restrict__ bzx, const float* __restrict__ Wdx,
                          const float* __restrict__ bdb, float* __restrict__ bcomp)
{
    int n = blockIdx.x * 256 + threadIdx.x;
    if (n < 2048) {
        int kk = n >> 9;
        float s = 0.f;
        for (int z = 0; z < HYP_; z++) s += bzh[kk * HYP_ + z] * Wdh[n * HYP_ + z];
        bcomp[n] = s;
    } else if (n < 4096) {
        int m = n - 2048; int kk = m >> 9;
        float s = 0.f;
        for (int z = 0; z < HYP_; z++) s += bzx[kk * HYP_ + z] * Wdx[m * HYP_ + z];
        bcomp[n] = s;
    } else {
        bcomp[n] = bdb[n - 4096];
    }
}

__global__ void init_zero(float* __restrict__ h, float* __restrict__ c,
                          float* __restrict__ tail)
{
    int i = blockIdx.x * 256 + threadIdx.x;
    h[i] = 0.f; c[i] = 0.f; tail[i] = 0.f;
}

// ---------------- fused elementwise + LayerNorm + LSTM cell ----------------
__global__ void __launch_bounds__(512)
lstm_step(const float* __restrict__ D, const float* __restrict__ wh,
          const float* __restrict__ wx, const float* __restrict__ lng,
          const float* __restrict__ lnb, float* __restrict__ h,
          float* __restrict__ c, float* __restrict__ out,
          float* __restrict__ hT, float* __restrict__ cT)
{
    const int b  = blockIdx.x;
    const int hh = threadIdx.x;
    const int lane = hh & 31, wrp = hh >> 5;
    __shared__ float red[4][16];
    __shared__ float mu_s[4], iv_s[4];

    float y[4];
    #pragma unroll
    for (int k = 0; k < 4; k++) {
        const int idx = k * H_ + hh;
        const int64_t base = (int64_t)b * 6144;
        float dh = D[base + idx];
        float dx = D[base + 2048 + idx];
        float db = D[base + 4096 + idx];
        y[k] = dh * wh[(int64_t)b * 2048 + idx] + dx * wx[(int64_t)b * 2048 + idx] + db;
    }
    #pragma unroll
    for (int k = 0; k < 4; k++) {
        float s = y[k];
        #pragma unroll
        for (int o = 16; o; o >>= 1) s += __shfl_xor_sync(0xffffffffu, s, o);
        if (lane == 0) red[k][wrp] = s;
    }
    __syncthreads();
    if (hh < 4) {
        float s = 0.f;
        #pragma unroll
        for (int w = 0; w < 16; w++) s += red[hh][w];
        mu_s[hh] = s * (1.0f / H_);
    }
    __syncthreads();
    const float mu[4] = {mu_s[0], mu_s[1], mu_s[2], mu_s[3]};
    #pragma unroll
    for (int k = 0; k < 4; k++) {
        float d = y[k] - mu[k];
        float s = d * d;
        #pragma unroll
        for (int o = 16; o; o >>= 1) s += __shfl_xor_sync(0xffffffffu, s, o);
        if (lane == 0) red[k][wrp] = s;
    }
    __syncthreads();
    if (hh < 4) {
        float s = 0.f;
        #pragma unroll
        for (int w = 0; w < 16; w++) s += red[hh][w];
        iv_s[hh] = rsqrtf(s * (1.0f / H_) + 1e-5f);
    }
    __syncthreads();

    float yn[4];
    #pragma unroll
    for (int k = 0; k < 4; k++)
        yn[k] = (y[k] - mu[k]) * iv_s[k] * lng[k * H_ + hh] + lnb[k * H_ + hh];

    const float ig = 1.f / (1.f + expf(-yn[0]));
    const float fg = 1.f / (1.f + expf(-yn[1]));
    const float gg = tanhf(yn[2]);
    const float og = 1.f / (1.f + expf(-yn[3]));

    const int64_t bi = (int64_t)b * H_ + hh;
    const float cn = fg * c[bi] + ig * gg;
    const float hn = og * tanhf(cn);
    c[bi] = cn;  h[bi] = hn;  out[bi] = hn;
    if (hT) { hT[bi] = hn; cT[bi] = cn; }
}

// ---------------- host driver ----------------
extern "C" void kernel_launch(void* const* d_in, const int* in_sizes, int n_in,
                              void* d_out, int out_size)
{
    const float* x    = (const float*)d_in[0];
    const float* meta = (const float*)d_in[1];
    const int*   inp  = (const int*)  d_in[2];
    const float* Wq   = (const float*)d_in[3];
    const float* bq   = (const float*)d_in[4];
    const float* Wk   = (const float*)d_in[5];
    const float* bk   = (const float*)d_in[6];
    const float* Wm   = (const float*)d_in[7];
    const float* bm   = (const float*)d_in[8];
    const float* Wzh  = (const float*)d_in[9];
    const float* bzh  = (const float*)d_in[10];
    const float* Wzx  = (const float*)d_in[11];
    const float* bzx  = (const float*)d_in[12];
    const float* Wzb  = (const float*)d_in[13];
    const float* Wdh  = (const float*)d_in[14];
    const float* Wdx  = (const float*)d_in[15];
    const float* Wdb  = (const float*)d_in[16];
    const float* bdb  = (const float*)d_in[17];
    const float* w_h  = (const float*)d_in[18];
    const float* w_x  = (const float*)d_in[19];
    const float* lng  = (const float*)d_in[20];
    const float* lnb  = (const float*)d_in[21];
    float* out = (float*)d_out;

    float *pq, *pk, *patt, *pmpre, *pwx, *pWzT, *pWcomp, *pbcomp,
          *pmerged, *pD, *pwh, *ph, *pc;
    cudaGetSymbolAddress((void**)&pq,     g_q);
    cudaGetSymbolAddress((void**)&pk,     g_k);
    cudaGetSymbolAddress((void**)&patt,   g_att);
    cudaGetSymbolAddress((void**)&pmpre,  g_mpre);
    cudaGetSymbolAddress((void**)&pwx,    g_wx);
    cudaGetSymbolAddress((void**)&pWzT,   g_WzT);
    cudaGetSymbolAddress((void**)&pWcomp, g_Wcomp);
    cudaGetSymbolAddress((void**)&pbcomp, g_bcomp);
    cudaGetSymbolAddress((void**)&pmerged,g_merged);
    cudaGetSymbolAddress((void**)&pD,     g_D);
    cudaGetSymbolAddress((void**)&pwh,    g_wh);
    cudaGetSymbolAddress((void**)&ph,     g_h);
    cudaGetSymbolAddress((void**)&pc,     g_c);

    // launch order arranged so ncu (-s 5 -c 1) samples the big wx tgemm (#5)
    init_zero<<<1024, 256>>>(ph, pc, out + OFF_HHAT);                       // 0
    tgemm<<<dim3(HYP_/128, (T_*B_)/128), 256>>>(                            // 1: q
        x, DIN_, Wq, DIN_, pq, HYP_, bq, nullptr, 0, DIN_, 0);
    tgemm<<<dim3(HYP_/128, (B_*L_)/128), 256>>>(                            // 2: k
        meta, DM_, Wk, DM_, pk, HYP_, bk, nullptr, 0, DM_, 0);
    tgemm<<<dim3(HYP_/128, (T_*B_)/128), 256>>>(                            // 3: mpre
        x, DIN_, Wm, DIN_ + DM_ + H_, pmpre, HYP_, bm, nullptr, 0, DIN_, 0);
    attn_kernel<<<T_ * B_, 256>>>(pq, pk, meta, inp, patt);                 // 4
    tgemm<<<dim3((4*H_)/128, (T_*B_)/128), 256>>>(                          // 5: wx (BIG)
        x, DIN_, w_x, DIN_, pwx, 4*H_, nullptr, nullptr, 0, DIN_, 0);
    tgemm<<<dim3(HYP_/128, (T_*B_)/128), 256>>>(                            // 6: mpre += att@Wm2
        patt, DM_, Wm + DIN_, DIN_ + DM_ + H_, pmpre, HYP_, nullptr, pmpre, HYP_, DM_, 0);

    // ---- weight preprocessing (fp32 exact) ----
    transpose_wz<<<3072, 256>>>(Wzh, Wzx, Wzb, pWzT);
    {
        dim3 gW(HYP_ / 128, H_ / 128, 4);
        const float* Wd[3] = {Wdh, Wdx, Wdb};
        for (int s = 0; s < 3; s++)
            sgemm128<<<gW, 256>>>(Wd[s], HYP_, (int64_t)H_ * HYP_,
                                  pWzT + (int64_t)s * 4 * HYP_ * HYP_, HYP_, (int64_t)HYP_ * HYP_,
                                  pWcomp + (int64_t)s * 4 * H_ * HYP_, HYP_, (int64_t)H_ * HYP_,
                                  nullptr, HYP_);
    }
    comp_bias<<<24, 256>>>(bzh, Wdh, bzx, Wdx, bdb, pbcomp);

    // ---- sequential scan: 3 launches per step ----
    for (int t = 0; t < T_; t++) {
        sgemm_merged<<<dim3(4, 16), 128>>>(ph, Wm + DIN_ + DM_,
                                           pmpre + (int64_t)t * B_ * HYP_, pmerged);
        tgemm_dwh<<<dim3(64, B_/128), 256>>>(ph, w_h, pmerged, pWcomp, pbcomp, pwh, pD);
        const bool last = (t == T_ - 1);
        lstm_step<<<B_, H_>>>(pD, pwh, pwx + (int64_t)t * B_ * 4 * H_, lng, lnb,
                              ph, pc, out + (int64_t)t * B_ * H_,
                              last ? out + OFF_HT : nullptr,
                              last ? out + OFF_CT : nullptr);
    }
}

// round 10
// speedup vs baseline: 2.1016x; 1.0046x over previous
#include <cuda_runtime.h>
#include <stdint.h>
#include <math.h>

// ---------------- problem constants ----------------
#define T_   128
#define B_   512
#define DIN_ 512
#define H_   512
#define DM_  256
#define HYP_ 256
#define L_   100

// output offsets (floats)
#define OUT_N      ((int64_t)T_*B_*H_)
#define OFF_HT     (OUT_N)
#define OFF_CT     (OFF_HT + (int64_t)B_*H_)
#define OFF_HHAT   (OFF_CT + (int64_t)B_*H_)

// ---------------- scratch (device globals) ----------------
__device__ float g_q   [(size_t)T_*B_*HYP_];
__device__ float g_k   [(size_t)B_*L_*HYP_];
__device__ float g_att [(size_t)T_*B_*DM_];
__device__ float g_mpre[(size_t)T_*B_*HYP_];
__device__ float g_wx  [(size_t)T_*B_*4*H_];
__device__ float g_WzT [3*4*HYP_*HYP_];
__device__ float g_Wcomp[3*4*H_*HYP_];
__device__ float g_bcomp[3*4*H_];
__device__ float g_merged[B_*HYP_];
__device__ float g_D  [(size_t)B_*3*4*H_];
__device__ float g_wh [(size_t)B_*4*H_];
__device__ float g_h  [B_*H_];
__device__ float g_c  [B_*H_];

// ================================================================
//  tf32 tensor-core GEMM:  C[m,n] = sum_k A[m,k] * W[n,k]
//  CTA tile 128x128, k-chunk 16, double buffered, 2 CTAs/SM.
//  Fragment layout in smem is bank-SWIZZLED: staging stores go from
//  8-way to 2-way conflicts; fragment loads remain LDS.128/LDS.64
//  conflict-free (swizzle is a bijection on the lane index).
// ================================================================
__device__ __forceinline__ uint32_t f2tf32(float f) {
    uint32_t u; asm("cvt.rna.tf32.f32 %0, %1;" : "=r"(u) : "f"(f)); return u;
}

__device__ __forceinline__ void mma_tf32(float* c, const uint32_t* a, const uint32_t* b) {
    asm volatile(
        "mma.sync.aligned.m16n8k8.row.col.f32.tf32.tf32.f32 "
        "{%0,%1,%2,%3}, {%4,%5,%6,%7}, {%8,%9}, {%0,%1,%2,%3};"
        : "+f"(c[0]), "+f"(c[1]), "+f"(c[2]), "+f"(c[3])
        : "r"(a[0]), "r"(a[1]), "r"(a[2]), "r"(a[3]), "r"(b[0]), "r"(b[1]));
}

// Stage a 128x16 A tile (rows m, cols k) into swizzled fragment layout.
// Fragment element (rr,k): t = (rr&7)*4 + (k&3); stored at tsw = t ^ ((t>>3)&3).
__device__ __forceinline__ void stageA(uint32_t* As, int tid, float4 v0, float4 v1) {
    const int r = tid >> 1, chalf = (tid & 1) << 3;
    const int i = r >> 4, rr = r & 15;
    float v[8] = {v0.x, v0.y, v0.z, v0.w, v1.x, v1.y, v1.z, v1.w};
    #pragma unroll
    for (int cc = 0; cc < 8; cc++) {
        const int c = chalf + cc;
        const int s = c >> 3, k = c & 7;
        const int t   = ((rr & 7) << 2) + (k & 3);
        const int tsw = t ^ ((t >> 3) & 3);
        const int reg = (rr >> 3) + ((k >> 2) << 1);
        As[(((s << 3) + i) << 7) + (tsw << 2) + reg] = f2tf32(v[cc]);
    }
}

// Stage a 128x16 W tile (rows n, cols k) into swizzled B fragment layout.
// t = rr*4 + (k&3); stored at tsw = t ^ ((t>>3)&3) ^ (j&1).
__device__ __forceinline__ void stageB(uint32_t* Bs, int tid, float4 v0, float4 v1) {
    const int r = tid >> 1, chalf = (tid & 1) << 3;
    const int j = r >> 3, rr = r & 7;
    float v[8] = {v0.x, v0.y, v0.z, v0.w, v1.x, v1.y, v1.z, v1.w};
    #pragma unroll
    for (int cc = 0; cc < 8; cc++) {
        const int c = chalf + cc;
        const int s = c >> 3, k = c & 7;
        const int t   = (rr << 2) + (k & 3);
        const int tsw = (t ^ ((t >> 3) & 3)) ^ (j & 1);
        const int reg = k >> 2;
        Bs[(((s << 4) + j) << 6) + (tsw << 1) + reg] = f2tf32(v[cc]);
    }
}

__device__ __forceinline__ void tgemm_core(
    const float* __restrict__ A, int lda,
    const float* __restrict__ W, int ldw,
    float* __restrict__ C, int ldc,
    const float* __restrict__ bias,
    const float* __restrict__ addsrc, int ldadd,
    int K, int relu, int64_t m0, int n0,
    uint32_t* As, uint32_t* Bs)
{
    const int tid  = threadIdx.x;
    const int lane = tid & 31, warp = tid >> 5;
    const int wm = warp >> 2, wn = warp & 3;        // wm 0..1, wn 0..3
    const int lswA  = lane ^ ((lane >> 3) & 3);     // A-frag load swizzle
    const int lswB0 = lswA;                         // B-frag, even j
    const int lswB1 = lswA ^ 1;                     // B-frag, odd j

    const float* Ap = A + (m0 + (tid >> 1)) * (int64_t)lda + ((tid & 1) << 3);
    const float* Wp = W + (int64_t)(n0 + (tid >> 1)) * ldw + ((tid & 1) << 3);

    float acc[4][4][4];
    #pragma unroll
    for (int i = 0; i < 4; i++)
        #pragma unroll
        for (int j = 0; j < 4; j++)
            #pragma unroll
            for (int p = 0; p < 4; p++) acc[i][j][p] = 0.f;

    float4 pa0 = *(const float4*)(Ap);
    float4 pa1 = *(const float4*)(Ap + 4);
    float4 pb0 = *(const float4*)(Wp);
    float4 pb1 = *(const float4*)(Wp + 4);
    stageA(As, tid, pa0, pa1);
    stageB(Bs, tid, pb0, pb1);
    __syncthreads();

    int buf = 0;
    for (int k0 = 0; k0 < K; k0 += 16) {
        const bool more = (k0 + 16) < K;
        if (more) {
            pa0 = *(const float4*)(Ap + k0 + 16);
            pa1 = *(const float4*)(Ap + k0 + 20);
            pb0 = *(const float4*)(Wp + k0 + 16);
            pb1 = *(const float4*)(Wp + k0 + 20);
        }
        const uint32_t* Ab = As + (buf << 11);
        const uint32_t* Bb = Bs + (buf << 11);
        #pragma unroll
        for (int s = 0; s < 2; s++) {
            uint32_t afr[4][4], bfr[4][2];
            #pragma unroll
            for (int mf = 0; mf < 4; mf++) {
                uint4 v = *(const uint4*)&Ab[(((s << 3) + (wm << 2) + mf) << 7) + (lswA << 2)];
                afr[mf][0] = v.x; afr[mf][1] = v.y; afr[mf][2] = v.z; afr[mf][3] = v.w;
            }
            #pragma unroll
            for (int nf = 0; nf < 4; nf++) {
                const int jg = (wn << 2) + nf;
                const int ls = (nf & 1) ? lswB1 : lswB0;
                uint2 v = *(const uint2*)&Bb[(((s << 4) + jg) << 6) + (ls << 1)];
                bfr[nf][0] = v.x; bfr[nf][1] = v.y;
            }
            #pragma unroll
            for (int mf = 0; mf < 4; mf++)
                #pragma unroll
                for (int nf = 0; nf < 4; nf++)
                    mma_tf32(acc[mf][nf], afr[mf], bfr[nf]);
        }
        if (more) {
            buf ^= 1;
            stageA(As + (buf << 11), tid, pa0, pa1);
            stageB(Bs + (buf << 11), tid, pb0, pb1);
            __syncthreads();
        }
    }

    // epilogue
    #pragma unroll
    for (int mf = 0; mf < 4; mf++) {
        const int64_t r0 = m0 + (wm << 6) + (mf << 4) + (lane >> 2);
        #pragma unroll
        for (int nf = 0; nf < 4; nf++) {
            const int col = n0 + (wn << 5) + (nf << 3) + ((lane & 3) << 1);
            float v0 = acc[mf][nf][0], v1 = acc[mf][nf][1];
            float v2 = acc[mf][nf][2], v3 = acc[mf][nf][3];
            if (bias) {
                float2 bb = *(const float2*)&bias[col];
                v0 += bb.x; v1 += bb.y; v2 += bb.x; v3 += bb.y;
            }
            if (addsrc) {
                float2 s0 = *(const float2*)&addsrc[r0 * ldadd + col];
                float2 s1 = *(const float2*)&addsrc[(r0 + 8) * ldadd + col];
                v0 += s0.x; v1 += s0.y; v2 += s1.x; v3 += s1.y;
            }
            if (relu) {
                v0 = fmaxf(v0, 0.f); v1 = fmaxf(v1, 0.f);
                v2 = fmaxf(v2, 0.f); v3 = fmaxf(v3, 0.f);
            }
            *(float2*)&C[r0 * ldc + col]       = make_float2(v0, v1);
            *(float2*)&C[(r0 + 8) * ldc + col] = make_float2(v2, v3);
        }
    }
}

__global__ void __launch_bounds__(256, 2)
tgemm(const float* __restrict__ A, int lda,
      const float* __restrict__ W, int ldw,
      float* __restrict__ C, int ldc,
      const float* __restrict__ bias,
      const float* __restrict__ addsrc, int ldadd,
      int K, int relu)
{
    __shared__ uint32_t As[2 * 2048];
    __shared__ uint32_t Bs[2 * 2048];
    tgemm_core(A, lda, W, ldw, C, ldc, bias, addsrc, ldadd, K, relu,
               (int64_t)blockIdx.y * 128, blockIdx.x * 128, As, Bs);
}

// per-step combined: bx<16 -> wh = h @ w_h^T ; else D = merged @ Wcomp^T + bcomp
__global__ void __launch_bounds__(256, 2)
tgemm_dwh(const float* __restrict__ h, const float* __restrict__ w_h,
          const float* __restrict__ merged, const float* __restrict__ Wcomp,
          const float* __restrict__ bcomp,
          float* __restrict__ wh, float* __restrict__ D)
{
    __shared__ uint32_t As[2 * 2048];
    __shared__ uint32_t Bs[2 * 2048];
    const int bx = blockIdx.x;
    const int64_t m0 = (int64_t)blockIdx.y * 128;
    if (bx < 16) {
        tgemm_core(h, H_, w_h, H_, wh, 4*H_, nullptr, nullptr, 0,
                   H_, 0, m0, bx * 128, As, Bs);
    } else {
        tgemm_core(merged, HYP_, Wcomp, HYP_, D, 3*4*H_, bcomp, nullptr, 0,
                   HYP_, 0, m0, (bx - 16) * 128, As, Bs);
    }
}

// ================================================================
//  scalar FFMA2 GEMM (tiny preproc GEMMs only)
// ================================================================
typedef unsigned long long u64;

__device__ __forceinline__ u64 dup2f(float a) {
    u64 r; asm("mov.b64 %0, {%1, %1};" : "=l"(r) : "f"(a)); return r;
}
__device__ __forceinline__ void fma2(u64 &c, u64 a, u64 b) {
    asm("fma.rn.f32x2 %0, %1, %2, %0;" : "+l"(c) : "l"(a), "l"(b));
}
__device__ __forceinline__ void unpk(u64 v, float &lo, float &hi) {
    asm("mov.b64 {%0, %1}, %2;" : "=f"(lo), "=f"(hi) : "l"(v));
}

__global__ void __launch_bounds__(256, 2)
sgemm128(const float* __restrict__ A, int lda, int64_t sA,
         const float* __restrict__ W, int ldw, int64_t sW,
         float* __restrict__ C, int ldc, int64_t sC,
         const float* __restrict__ bias, int K)
{
    __shared__ float As[2][16][128];
    __shared__ float Ws[2][16][128];
    const int bz = blockIdx.z;
    A += bz * sA;  W += bz * sW;  C += bz * sC;
    const int64_t m0 = (int64_t)blockIdx.y * 128;
    const int n0 = blockIdx.x * 128;

    const int tid = threadIdx.x;
    const int lr = tid >> 1;
    const int lk = (tid & 1) << 3;
    const float* Ap = A + (m0 + lr) * (int64_t)lda + lk;
    const float* Wp = W + (int64_t)(n0 + lr) * ldw + lk;
    const int tx = tid & 15, ty = tid >> 4;

    u64 acc[8][4];
    #pragma unroll
    for (int i = 0; i < 8; i++)
        #pragma unroll
        for (int j = 0; j < 4; j++) acc[i][j] = 0ull;

    float4 pa0 = *(const float4*)(Ap);
    float4 pa1 = *(const float4*)(Ap + 4);
    float4 pw0 = *(const float4*)(Wp);
    float4 pw1 = *(const float4*)(Wp + 4);
    As[0][lk+0][lr]=pa0.x; As[0][lk+1][lr]=pa0.y; As[0][lk+2][lr]=pa0.z; As[0][lk+3][lr]=pa0.w;
    As[0][lk+4][lr]=pa1.x; As[0][lk+5][lr]=pa1.y; As[0][lk+6][lr]=pa1.z; As[0][lk+7][lr]=pa1.w;
    Ws[0][lk+0][lr]=pw0.x; Ws[0][lk+1][lr]=pw0.y; Ws[0][lk+2][lr]=pw0.z; Ws[0][lk+3][lr]=pw0.w;
    Ws[0][lk+4][lr]=pw1.x; Ws[0][lk+5][lr]=pw1.y; Ws[0][lk+6][lr]=pw1.z; Ws[0][lk+7][lr]=pw1.w;
    __syncthreads();

    int buf = 0;
    for (int k0 = 0; k0 < K; k0 += 16) {
        const bool more = (k0 + 16) < K;
        if (more) {
            pa0 = *(const float4*)(Ap + k0 + 16);
            pa1 = *(const float4*)(Ap + k0 + 20);
            pw0 = *(const float4*)(Wp + k0 + 16);
            pw1 = *(const float4*)(Wp + k0 + 20);
        }
        #pragma unroll
        for (int kk = 0; kk < 16; kk++) {
            float4 a0 = *(const float4*)&As[buf][kk][ty << 3];
            float4 a1 = *(const float4*)&As[buf][kk][(ty << 3) + 4];
            const u64* bp = (const u64*)&Ws[buf][kk][tx << 3];
            u64 b0 = bp[0], b1 = bp[1], b2 = bp[2], b3 = bp[3];
            float am[8] = {a0.x, a0.y, a0.z, a0.w, a1.x, a1.y, a1.z, a1.w};
            #pragma unroll
            for (int i = 0; i < 8; i++) {
                u64 ad = dup2f(am[i]);
                fma2(acc[i][0], ad, b0);
                fma2(acc[i][1], ad, b1);
                fma2(acc[i][2], ad, b2);
                fma2(acc[i][3], ad, b3);
            }
        }
        if (more) {
            const int nb = buf ^ 1;
            As[nb][lk+0][lr]=pa0.x; As[nb][lk+1][lr]=pa0.y; As[nb][lk+2][lr]=pa0.z; As[nb][lk+3][lr]=pa0.w;
            As[nb][lk+4][lr]=pa1.x; As[nb][lk+5][lr]=pa1.y; As[nb][lk+6][lr]=pa1.z; As[nb][lk+7][lr]=pa1.w;
            Ws[nb][lk+0][lr]=pw0.x; Ws[nb][lk+1][lr]=pw0.y; Ws[nb][lk+2][lr]=pw0.z; Ws[nb][lk+3][lr]=pw0.w;
            Ws[nb][lk+4][lr]=pw1.x; Ws[nb][lk+5][lr]=pw1.y; Ws[nb][lk+6][lr]=pw1.z; Ws[nb][lk+7][lr]=pw1.w;
            __syncthreads();
            buf = nb;
        }
    }

    const int nc = n0 + (tx << 3);
    #pragma unroll
    for (int i = 0; i < 8; i++) {
        const int64_t row = m0 + (ty << 3) + i;
        float r[8];
        #pragma unroll
        for (int p = 0; p < 4; p++) {
            float lo, hi; unpk(acc[i][p], lo, hi);
            r[2*p] = lo; r[2*p+1] = hi;
        }
        if (bias) {
            float4 q0 = *(const float4*)&bias[nc];
            float4 q1 = *(const float4*)&bias[nc + 4];
            r[0]+=q0.x; r[1]+=q0.y; r[2]+=q0.z; r[3]+=q0.w;
            r[4]+=q1.x; r[5]+=q1.y; r[6]+=q1.z; r[7]+=q1.w;
        }
        *(float4*)&C[row * (int64_t)ldc + nc]     = make_float4(r[0], r[1], r[2], r[3]);
        *(float4*)&C[row * (int64_t)ldc + nc + 4] = make_float4(r[4], r[5], r[6], r[7]);
    }
}

// ---------------- small scalar GEMM: merged = relu(mpre + h @ Wm3^T) ----------------
__global__ void __launch_bounds__(128)
sgemm_merged(const float* __restrict__ h, const float* __restrict__ Wm3,
             const float* __restrict__ mpre, float* __restrict__ mg)
{
    __shared__ float As[2][16][32];
    __shared__ float Ws[2][16][64];
    const int n0 = blockIdx.x << 6;
    const int m0 = blockIdx.y << 5;
    const int tid = threadIdx.x;
    const int ar = tid >> 2, ak = (tid & 3) << 2;
    const int wr = tid >> 1, wk = (tid & 1) << 3;
    const float* Ap = h + (m0 + ar) * H_ + ak;
    const float* Wp = Wm3 + (int64_t)(n0 + wr) * (DIN_ + DM_ + H_) + wk;
    const int tx = tid & 15, ty = tid >> 4;

    float acc[4][4] = {};
    float4 a  = *(const float4*)(Ap);
    float4 w0 = *(const float4*)(Wp);
    float4 w1 = *(const float4*)(Wp + 4);
    As[0][ak+0][ar]=a.x; As[0][ak+1][ar]=a.y; As[0][ak+2][ar]=a.z; As[0][ak+3][ar]=a.w;
    Ws[0][wk+0][wr]=w0.x; Ws[0][wk+1][wr]=w0.y; Ws[0][wk+2][wr]=w0.z; Ws[0][wk+3][wr]=w0.w;
    Ws[0][wk+4][wr]=w1.x; Ws[0][wk+5][wr]=w1.y; Ws[0][wk+6][wr]=w1.z; Ws[0][wk+7][wr]=w1.w;
    __syncthreads();

    int buf = 0;
    for (int k0 = 0; k0 < H_; k0 += 16) {
        const bool more = (k0 + 16) < H_;
        if (more) {
            a  = *(const float4*)(Ap + k0 + 16);
            w0 = *(const float4*)(Wp + k0 + 16);
            w1 = *(const float4*)(Wp + k0 + 20);
        }
        #pragma unroll
        for (int kk = 0; kk < 16; kk++) {
            float4 av = *(const float4*)&As[buf][kk][ty << 2];
            float4 wv = *(const float4*)&Ws[buf][kk][tx << 2];
            float am[4] = {av.x, av.y, av.z, av.w};
            float wn[4] = {wv.x, wv.y, wv.z, wv.w};
            #pragma unroll
            for (int i = 0; i < 4; i++)
                #pragma unroll
                for (int j = 0; j < 4; j++)
                    acc[i][j] += am[i] * wn[j];
        }
        if (more) {
            const int nb = buf ^ 1;
            As[nb][ak+0][ar]=a.x; As[nb][ak+1][ar]=a.y; As[nb][ak+2][ar]=a.z; As[nb][ak+3][ar]=a.w;
            Ws[nb][wk+0][wr]=w0.x; Ws[nb][wk+1][wr]=w0.y; Ws[nb][wk+2][wr]=w0.z; Ws[nb][wk+3][wr]=w0.w;
            Ws[nb][wk+4][wr]=w1.x; Ws[nb][wk+5][wr]=w1.y; Ws[nb][wk+6][wr]=w1.z; Ws[nb][wk+7][wr]=w1.w;
            __syncthreads();
            buf = nb;
        }
    }
    const int nc = n0 + (tx << 2);
    #pragma unroll
    for (int i = 0; i < 4; i++) {
        const int row = m0 + (ty << 2) + i;
        float4 s = *(const float4*)&mpre[row * HYP_ + nc];
        float4 r;
        r.x = fmaxf(acc[i][0] + s.x, 0.f);
        r.y = fmaxf(acc[i][1] + s.y, 0.f);
        r.z = fmaxf(acc[i][2] + s.z, 0.f);
        r.w = fmaxf(acc[i][3] + s.w, 0.f);
        *(float4*)&mg[row * HYP_ + nc] = r;
    }
}

// ---------------- fused attention ----------------
__global__ void __launch_bounds__(256)
attn_kernel(const float* __restrict__ q, const float* __restrict__ k,
            const float* __restrict__ meta, const int* __restrict__ inp,
            float* __restrict__ att)
{
    const int tb = blockIdx.x;
    const int b  = tb & (B_ - 1);
    const int tid = threadIdx.x;
    __shared__ float qs[HYP_];
    __shared__ float sc[128];

    qs[tid] = q[(int64_t)tb * HYP_ + tid] * 0.0625f;
    __syncthreads();

    const int lane = tid & 31, wrp = tid >> 5;
    for (int l = wrp; l < L_; l += 8) {
        const float* kp = k + ((int64_t)b * L_ + l) * HYP_;
        float s = 0.f;
        #pragma unroll
        for (int e = 0; e < HYP_ / 32; e++)
            s += qs[lane + 32 * e] * kp[lane + 32 * e];
        #pragma unroll
        for (int o = 16; o; o >>= 1) s += __shfl_xor_sync(0xffffffffu, s, o);
        if (lane == 0) sc[l] = (inp[b * L_ + l] == 0) ? -1e9f : s;
    }
    __syncthreads();

    if (tid < 32) {
        float v[4]; float m = -3.0e38f;
        #pragma unroll
        for (int j = 0; j < 4; j++) {
            int l = tid + 32 * j;
            v[j] = (l < L_) ? sc[l] : -3.0e38f;
            m = fmaxf(m, v[j]);
        }
        #pragma unroll
        for (int o = 16; o; o >>= 1) m = fmaxf(m, __shfl_xor_sync(0xffffffffu, m, o));
        float s = 0.f;
        #pragma unroll
        for (int j = 0; j < 4; j++) { v[j] = expf(v[j] - m); s += v[j]; }
        #pragma unroll
        for (int o = 16; o; o >>= 1) s += __shfl_xor_sync(0xffffffffu, s, o);
        const float inv = 1.0f / s;
        #pragma unroll
        for (int j = 0; j < 4; j++) {
            int l = tid + 32 * j;
            if (l < L_) sc[l] = v[j] * inv;
        }
    }
    __syncthreads();

    float acc = 0.f;
    const float* mp = meta + (int64_t)b * L_ * DM_ + tid;
    #pragma unroll 4
    for (int l = 0; l < L_; l++) acc += sc[l] * mp[(int64_t)l * DM_];
    att[(int64_t)tb * DM_ + tid] = acc;
}

// ---------------- weight preprocessing ----------------
__global__ void transpose_wz(const float* __restrict__ Wzh, const float* __restrict__ Wzx,
                             const float* __restrict__ Wzb, float* __restrict__ WzT)
{
    int idx = blockIdx.x * 256 + threadIdx.x;
    int s  = idx / (4 * HYP_ * HYP_);
    int r  = idx % (4 * HYP_ * HYP_);
    int kk = r / (HYP_ * HYP_);
    int r2 = r % (HYP_ * HYP_);
    int z  = r2 / HYP_;
    int z2 = r2 % HYP_;
    const float* Wz = (s == 0) ? Wzh : ((s == 1) ? Wzx : Wzb);
    WzT[idx] = Wz[(kk * HYP_ + z2) * HYP_ + z];
}

__global__ void comp_bias(const float* __restrict__ bzh, const float* __restrict__ Wdh,
                          const float* __restrict__ bzx, const float* __restrict__ Wdx,
                          const float* __restrict__ bdb, float* __restrict__ bcomp)
{
    int n = blockIdx.x * 256 + threadIdx.x;
    if (n < 2048) {
        int kk = n >> 9;
        float s = 0.f;
        for (int z = 0; z < HYP_; z++) s += bzh[kk * HYP_ + z] * Wdh[n * HYP_ + z];
        bcomp[n] = s;
    } else if (n < 4096) {
        int m = n - 2048; int kk = m >> 9;
        float s = 0.f;
        for (int z = 0; z < HYP_; z++) s += bzx[kk * HYP_ + z] * Wdx[m * HYP_ + z];
        bcomp[n] = s;
    } else {
        bcomp[n] = bdb[n - 4096];
    }
}

__global__ void init_zero(float* __restrict__ h, float* __restrict__ c,
                          float* __restrict__ tail)
{
    int i = blockIdx.x * 256 + threadIdx.x;
    h[i] = 0.f; c[i] = 0.f; tail[i] = 0.f;
}

// ---------------- fused elementwise + LayerNorm + LSTM cell ----------------
__global__ void __launch_bounds__(512)
lstm_step(const float* __restrict__ D, const float* __restrict__ wh,
          const float* __restrict__ wx, const float* __restrict__ lng,
          const float* __restrict__ lnb, float* __restrict__ h,
          float* __restrict__ c, float* __restrict__ out,
          float* __restrict__ hT, float* __restrict__ cT)
{
    const int b  = blockIdx.x;
    const int hh = threadIdx.x;
    const int lane = hh & 31, wrp = hh >> 5;
    __shared__ float red[4][16];
    __shared__ float mu_s[4], iv_s[4];

    float y[4];
    #pragma unroll
    for (int k = 0; k < 4; k++) {
        const int idx = k * H_ + hh;
        const int64_t base = (int64_t)b * 6144;
        float dh = D[base + idx];
        float dx = D[base + 2048 + idx];
        float db = D[base + 4096 + idx];
        y[k] = dh * wh[(int64_t)b * 2048 + idx] + dx * wx[(int64_t)b * 2048 + idx] + db;
    }
    #pragma unroll
    for (int k = 0; k < 4; k++) {
        float s = y[k];
        #pragma unroll
        for (int o = 16; o; o >>= 1) s += __shfl_xor_sync(0xffffffffu, s, o);
        if (lane == 0) red[k][wrp] = s;
    }
    __syncthreads();
    if (hh < 4) {
        float s = 0.f;
        #pragma unroll
        for (int w = 0; w < 16; w++) s += red[hh][w];
        mu_s[hh] = s * (1.0f / H_);
    }
    __syncthreads();
    const float mu[4] = {mu_s[0], mu_s[1], mu_s[2], mu_s[3]};
    #pragma unroll
    for (int k = 0; k < 4; k++) {
        float d = y[k] - mu[k];
        float s = d * d;
        #pragma unroll
        for (int o = 16; o; o >>= 1) s += __shfl_xor_sync(0xffffffffu, s, o);
        if (lane == 0) red[k][wrp] = s;
    }
    __syncthreads();
    if (hh < 4) {
        float s = 0.f;
        #pragma unroll
        for (int w = 0; w < 16; w++) s += red[hh][w];
        iv_s[hh] = rsqrtf(s * (1.0f / H_) + 1e-5f);
    }
    __syncthreads();

    float yn[4];
    #pragma unroll
    for (int k = 0; k < 4; k++)
        yn[k] = (y[k] - mu[k]) * iv_s[k] * lng[k * H_ + hh] + lnb[k * H_ + hh];

    const float ig = 1.f / (1.f + expf(-yn[0]));
    const float fg = 1.f / (1.f + expf(-yn[1]));
    const float gg = tanhf(yn[2]);
    const float og = 1.f / (1.f + expf(-yn[3]));

    const int64_t bi = (int64_t)b * H_ + hh;
    const float cn = fg * c[bi] + ig * gg;
    const float hn = og * tanhf(cn);
    c[bi] = cn;  h[bi] = hn;  out[bi] = hn;
    if (hT) { hT[bi] = hn; cT[bi] = cn; }
}

// ---------------- host driver ----------------
extern "C" void kernel_launch(void* const* d_in, const int* in_sizes, int n_in,
                              void* d_out, int out_size)
{
    const float* x    = (const float*)d_in[0];
    const float* meta = (const float*)d_in[1];
    const int*   inp  = (const int*)  d_in[2];
    const float* Wq   = (const float*)d_in[3];
    const float* bq   = (const float*)d_in[4];
    const float* Wk   = (const float*)d_in[5];
    const float* bk   = (const float*)d_in[6];
    const float* Wm   = (const float*)d_in[7];
    const float* bm   = (const float*)d_in[8];
    const float* Wzh  = (const float*)d_in[9];
    const float* bzh  = (const float*)d_in[10];
    const float* Wzx  = (const float*)d_in[11];
    const float* bzx  = (const float*)d_in[12];
    const float* Wzb  = (const float*)d_in[13];
    const float* Wdh  = (const float*)d_in[14];
    const float* Wdx  = (const float*)d_in[15];
    const float* Wdb  = (const float*)d_in[16];
    const float* bdb  = (const float*)d_in[17];
    const float* w_h  = (const float*)d_in[18];
    const float* w_x  = (const float*)d_in[19];
    const float* lng  = (const float*)d_in[20];
    const float* lnb  = (const float*)d_in[21];
    float* out = (float*)d_out;

    float *pq, *pk, *patt, *pmpre, *pwx, *pWzT, *pWcomp, *pbcomp,
          *pmerged, *pD, *pwh, *ph, *pc;
    cudaGetSymbolAddress((void**)&pq,     g_q);
    cudaGetSymbolAddress((void**)&pk,     g_k);
    cudaGetSymbolAddress((void**)&patt,   g_att);
    cudaGetSymbolAddress((void**)&pmpre,  g_mpre);
    cudaGetSymbolAddress((void**)&pwx,    g_wx);
    cudaGetSymbolAddress((void**)&pWzT,   g_WzT);
    cudaGetSymbolAddress((void**)&pWcomp, g_Wcomp);
    cudaGetSymbolAddress((void**)&pbcomp, g_bcomp);
    cudaGetSymbolAddress((void**)&pmerged,g_merged);
    cudaGetSymbolAddress((void**)&pD,     g_D);
    cudaGetSymbolAddress((void**)&pwh,    g_wh);
    cudaGetSymbolAddress((void**)&ph,     g_h);
    cudaGetSymbolAddress((void**)&pc,     g_c);

    // launch order arranged so ncu (-s 5 -c 1) samples the big wx tgemm (#5)
    init_zero<<<1024, 256>>>(ph, pc, out + OFF_HHAT);                       // 0
    tgemm<<<dim3(HYP_/128, (T_*B_)/128), 256>>>(                            // 1: q
        x, DIN_, Wq, DIN_, pq, HYP_, bq, nullptr, 0, DIN_, 0);
    tgemm<<<dim3(HYP_/128, (B_*L_)/128), 256>>>(                            // 2: k
        meta, DM_, Wk, DM_, pk, HYP_, bk, nullptr, 0, DM_, 0);
    tgemm<<<dim3(HYP_/128, (T_*B_)/128), 256>>>(                            // 3: mpre
        x, DIN_, Wm, DIN_ + DM_ + H_, pmpre, HYP_, bm, nullptr, 0, DIN_, 0);
    attn_kernel<<<T_ * B_, 256>>>(pq, pk, meta, inp, patt);                 // 4
    tgemm<<<dim3((4*H_)/128, (T_*B_)/128), 256>>>(                          // 5: wx (BIG)
        x, DIN_, w_x, DIN_, pwx, 4*H_, nullptr, nullptr, 0, DIN_, 0);
    tgemm<<<dim3(HYP_/128, (T_*B_)/128), 256>>>(                            // 6: mpre += att@Wm2
        patt, DM_, Wm + DIN_, DIN_ + DM_ + H_, pmpre, HYP_, nullptr, pmpre, HYP_, DM_, 0);

    // ---- weight preprocessing (fp32 exact) ----
    transpose_wz<<<3072, 256>>>(Wzh, Wzx, Wzb, pWzT);
    {
        dim3 gW(HYP_ / 128, H_ / 128, 4);
        const float* Wd[3] = {Wdh, Wdx, Wdb};
        for (int s = 0; s < 3; s++)
            sgemm128<<<gW, 256>>>(Wd[s], HYP_, (int64_t)H_ * HYP_,
                                  pWzT + (int64_t)s * 4 * HYP_ * HYP_, HYP_, (int64_t)HYP_ * HYP_,
                                  pWcomp + (int64_t)s * 4 * H_ * HYP_, HYP_, (int64_t)H_ * HYP_,
                                  nullptr, HYP_);
    }
    comp_bias<<<24, 256>>>(bzh, Wdh, bzx, Wdx, bdb, pbcomp);

    // ---- sequential scan: 3 launches per step ----
    for (int t = 0; t < T_; t++) {
        sgemm_merged<<<dim3(4, 16), 128>>>(ph, Wm + DIN_ + DM_,
                                           pmpre + (int64_t)t * B_ * HYP_, pmerged);
        tgemm_dwh<<<dim3(64, B_/128), 256>>>(ph, w_h, pmerged, pWcomp, pbcomp, pwh, pD);
        const bool last = (t == T_ - 1);
        lstm_step<<<B_, H_>>>(pD, pwh, pwx + (int64_t)t * B_ * 4 * H_, lng, lnb,
                              ph, pc, out + (int64_t)t * B_ * H_,
                              last ? out + OFF_HT : nullptr,
                              last ? out + OFF_CT : nullptr);
    }
}